// round 1
// baseline (speedup 1.0000x reference)
#include <cuda_runtime.h>
#include <math.h>

#define BB 2
#define SS 1024
#define DD 256
#define HH 4
#define CC 64
#define WINSZ 10
#define NITER 2
#define MM (BB*SS)          /* 2048 rows */
#define HID (8*DD)          /* 2048 */
#define BSD (BB*SS*DD)      /* 524288 */

// ---------------- scratch (static device globals; no allocation) ------------
__device__ float g_tmpA[BSD];
__device__ float g_tmpB[BSD];
__device__ float g_tmpC[BSD];
__device__ float g_Q[BSD];
__device__ float g_K[BSD];
__device__ float g_V[BSD];
__device__ float g_G[BSD];
__device__ float g_ctx[BSD];
__device__ float g_hid[(size_t)MM * HID];

// ---------------- LayerNorm: one block per row, 256 threads -----------------
__global__ void ln_kernel(const float* __restrict__ x, const float* __restrict__ g,
                          const float* __restrict__ b, float* __restrict__ out)
{
    int row = blockIdx.x;
    int t   = threadIdx.x;
    float v = x[(size_t)row * DD + t];

    __shared__ float red[8];
    __shared__ float mean_s, rstd_s;

    float s = v;
    #pragma unroll
    for (int o = 16; o > 0; o >>= 1) s += __shfl_xor_sync(0xffffffffu, s, o);
    if ((t & 31) == 0) red[t >> 5] = s;
    __syncthreads();
    if (t == 0) {
        float tot = 0.f;
        #pragma unroll
        for (int i = 0; i < 8; i++) tot += red[i];
        mean_s = tot * (1.0f / DD);
    }
    __syncthreads();
    float mean = mean_s;
    float d = v - mean;

    s = d * d;
    #pragma unroll
    for (int o = 16; o > 0; o >>= 1) s += __shfl_xor_sync(0xffffffffu, s, o);
    if ((t & 31) == 0) red[t >> 5] = s;
    __syncthreads();
    if (t == 0) {
        float tot = 0.f;
        #pragma unroll
        for (int i = 0; i < 8; i++) tot += red[i];
        rstd_s = rsqrtf(tot * (1.0f / DD) + 1e-5f);
    }
    __syncthreads();
    out[(size_t)row * DD + t] = d * rstd_s * g[t] + b[t];
}

// ---------------- generic tiled SGEMM body ----------------------------------
// C[M,N] = epilogue(A[M,K] @ B[K,N] + bias) (+ res). mode: 0=none 1=relu 2=sigmoid
template<int BM, int BN, int BK, int TM, int TN>
__device__ __forceinline__ void gemm_body(
    const float* __restrict__ A, const float* __restrict__ Bm,
    const float* __restrict__ bias, const float* __restrict__ res,
    float* __restrict__ Cm, int M, int N, int K, int mode)
{
    constexpr int TX = BN / TN;
    constexpr int TY = BM / TM;
    constexpr int THREADS = TX * TY;

    __shared__ float As[BK][BM + 4];
    __shared__ float Bs[BK][BN + 4];

    int tid = threadIdx.x;
    int tx  = tid % TX;
    int ty  = tid / TX;
    int row0 = blockIdx.y * BM;
    int col0 = blockIdx.x * BN;

    float acc[TM][TN];
    #pragma unroll
    for (int i = 0; i < TM; i++)
        #pragma unroll
        for (int j = 0; j < TN; j++) acc[i][j] = 0.f;

    for (int k0 = 0; k0 < K; k0 += BK) {
        #pragma unroll
        for (int i = tid; i < BM * BK; i += THREADS) {
            int r = i / BK, c = i % BK;
            As[c][r] = A[(size_t)(row0 + r) * K + k0 + c];
        }
        #pragma unroll
        for (int i = tid; i < BK * BN; i += THREADS) {
            int r = i / BN, c = i % BN;
            Bs[r][c] = Bm[(size_t)(k0 + r) * N + col0 + c];
        }
        __syncthreads();

        #pragma unroll
        for (int kk = 0; kk < BK; kk++) {
            float ra[TM], rb[TN];
            #pragma unroll
            for (int i = 0; i < TM; i++) ra[i] = As[kk][ty * TM + i];
            #pragma unroll
            for (int j = 0; j < TN; j++) rb[j] = Bs[kk][tx * TN + j];
            #pragma unroll
            for (int i = 0; i < TM; i++)
                #pragma unroll
                for (int j = 0; j < TN; j++)
                    acc[i][j] = fmaf(ra[i], rb[j], acc[i][j]);
        }
        __syncthreads();
    }

    #pragma unroll
    for (int i = 0; i < TM; i++) {
        int r = row0 + ty * TM + i;
        #pragma unroll
        for (int j = 0; j < TN; j++) {
            int c = col0 + tx * TN + j;
            float v = acc[i][j];
            if (bias) v += bias[c];
            if (mode == 1)      v = fmaxf(v, 0.f);
            else if (mode == 2) v = 1.f / (1.f + __expf(-v));
            if (res) v += res[(size_t)r * N + c];
            Cm[(size_t)r * N + c] = v;
        }
    }
}

__global__ void __launch_bounds__(256)
gemm64_kernel(const float* __restrict__ A, const float* __restrict__ Bm,
              const float* __restrict__ bias, const float* __restrict__ res,
              float* __restrict__ Cm, int M, int N, int K, int mode)
{
    gemm_body<64, 64, 16, 4, 4>(A, Bm, bias, res, Cm, M, N, K, mode);
}

__global__ void __launch_bounds__(256)
gemm128_kernel(const float* __restrict__ A, const float* __restrict__ Bm,
               const float* __restrict__ bias, const float* __restrict__ res,
               float* __restrict__ Cm, int M, int N, int K, int mode)
{
    gemm_body<128, 128, 16, 8, 8>(A, Bm, bias, res, Cm, M, N, K, mode);
}

// Fused Q/K/V/G projections: blockIdx.z selects which projection.
__global__ void __launch_bounds__(256)
qkvg_kernel(const float* __restrict__ xq, const float* __restrict__ xkv,
            const float* __restrict__ Wq, const float* __restrict__ Wk,
            const float* __restrict__ Wv, const float* __restrict__ Gw,
            const float* __restrict__ Gb)
{
    int z = blockIdx.z;
    const float* A    = (z == 0) ? xq : xkv;
    const float* W    = (z == 0) ? Wq : (z == 1) ? Wk : (z == 2) ? Wv : Gw;
    const float* bias = (z == 3) ? Gb : nullptr;
    float* C          = (z == 0) ? g_Q : (z == 1) ? g_K : (z == 2) ? g_V : g_G;
    int mode          = (z == 3) ? 2 : 0;
    gemm_body<64, 64, 16, 4, 4>(A, W, bias, nullptr, C, MM, DD, DD, mode);
}

// ---------------- windowed attention core: one warp per (n,h,s) -------------
// ctx[n,s,h*64+c] = (softmax_t(Q.K/8 with window+mask) @ V) * G
__global__ void __launch_bounds__(256)
attn_core_kernel(const unsigned char* __restrict__ mask)
{
    int idx  = blockIdx.x * blockDim.x + threadIdx.x;
    int gw   = idx >> 5;
    int lane = idx & 31;
    if (gw >= BB * HH * SS) return;

    int s = gw & (SS - 1);
    int h = (gw >> 10) & (HH - 1);
    int n = gw >> 12;

    int base_q = (n * SS + s) * DD + h * CC;
    float q0 = g_Q[base_q + lane];
    float q1 = g_Q[base_q + 32 + lane];

    int t0 = s - WINSZ; if (t0 < 0) t0 = 0;
    int t1 = s + WINSZ; if (t1 > SS - 1) t1 = SS - 1;
    int cnt = t1 - t0 + 1;

    float sc[2 * WINSZ + 1];
    float mx = -1e30f;
    for (int i = 0; i < cnt; i++) {
        int t = t0 + i;
        float v;
        if (mask[n * SS + t]) {
            v = -1e30f;
        } else {
            int bk = (n * SS + t) * DD + h * CC;
            float p = q0 * g_K[bk + lane] + q1 * g_K[bk + 32 + lane];
            #pragma unroll
            for (int o = 16; o > 0; o >>= 1) p += __shfl_xor_sync(0xffffffffu, p, o);
            v = p * 0.125f;
        }
        sc[i] = v;
        mx = fmaxf(mx, v);
    }

    float denom = 0.f;
    for (int i = 0; i < cnt; i++) {
        float e = (sc[i] <= -1e29f) ? 0.f : __expf(sc[i] - mx);
        sc[i] = e;
        denom += e;
    }
    float inv = (denom > 0.f) ? (1.f / denom) : 0.f;

    float o0 = 0.f, o1 = 0.f;
    for (int i = 0; i < cnt; i++) {
        int bv = (n * SS + (t0 + i)) * DD + h * CC;
        float a = sc[i] * inv;
        o0 = fmaf(a, g_V[bv + lane], o0);
        o1 = fmaf(a, g_V[bv + 32 + lane], o1);
    }
    g_ctx[base_q + lane]      = o0 * g_G[base_q + lane];
    g_ctx[base_q + 32 + lane] = o1 * g_G[base_q + 32 + lane];
}

// ---------------- host orchestration ----------------------------------------
extern "C" void kernel_launch(void* const* d_in, const int* in_sizes, int n_in,
                              void* d_out, int out_size)
{
    (void)in_sizes; (void)n_in; (void)out_size;

    const float* inL = (const float*)d_in[0];
    const float* inN = (const float*)d_in[1];
    const float* inO = (const float*)d_in[2];
    const unsigned char* mask = (const unsigned char*)d_in[3];
    const float* aWq = (const float*)d_in[4];
    const float* aWk = (const float*)d_in[5];
    const float* aWv = (const float*)d_in[6];
    const float* aGw = (const float*)d_in[7];
    const float* aGb = (const float*)d_in[8];
    const float* aOw = (const float*)d_in[9];
    const float* aOb = (const float*)d_in[10];
    const float* ln_g = (const float*)d_in[11];
    const float* ln_b = (const float*)d_in[12];
    const float* ff_g = (const float*)d_in[13];
    const float* ff_b = (const float*)d_in[14];
    const float* ff_w1 = (const float*)d_in[15];
    const float* ff_b1 = (const float*)d_in[16];
    const float* ff_w2 = (const float*)d_in[17];
    const float* ff_b2 = (const float*)d_in[18];

    float* L  = (float*)d_out;
    float* Nb = L + BSD;
    float* O  = Nb + BSD;

    cudaMemcpyAsync(L,  inL, (size_t)BSD * sizeof(float), cudaMemcpyDeviceToDevice);
    cudaMemcpyAsync(Nb, inN, (size_t)BSD * sizeof(float), cudaMemcpyDeviceToDevice);
    cudaMemcpyAsync(O,  inO, (size_t)BSD * sizeof(float), cudaMemcpyDeviceToDevice);

    void *p_tA, *p_tB, *p_tC, *p_ctx, *p_hid;
    cudaGetSymbolAddress(&p_tA,  g_tmpA);
    cudaGetSymbolAddress(&p_tB,  g_tmpB);
    cudaGetSymbolAddress(&p_tC,  g_tmpC);
    cudaGetSymbolAddress(&p_ctx, g_ctx);
    cudaGetSymbolAddress(&p_hid, g_hid);
    float* tA  = (float*)p_tA;
    float* tB  = (float*)p_tB;
    float* tC  = (float*)p_tC;
    float* ctx = (float*)p_ctx;
    float* hid = (float*)p_hid;

    auto run_ln = [&](const float* x, const float* g, const float* b, float* out) {
        ln_kernel<<<MM, DD>>>(x, g, b, out);
    };

    auto run_attn = [&](int k, const float* xq, const float* xkv, float* x) {
        dim3 gq(DD / 64, MM / 64, 4);
        qkvg_kernel<<<gq, 256>>>(xq, xkv,
                                 aWq + (size_t)k * DD * DD,
                                 aWk + (size_t)k * DD * DD,
                                 aWv + (size_t)k * DD * DD,
                                 aGw + (size_t)k * DD * DD,
                                 aGb + (size_t)k * DD);
        attn_core_kernel<<<(BB * HH * SS * 32) / 256, 256>>>(mask);
        dim3 gp(DD / 64, MM / 64);
        gemm64_kernel<<<gp, 256>>>(ctx, aOw + (size_t)k * DD * DD,
                                   aOb + (size_t)k * DD, x, x, MM, DD, DD, 0);
    };

    auto run_ff = [&](int k, float* x) {
        run_ln(x, ff_g + (size_t)k * DD, ff_b + (size_t)k * DD, tA);
        dim3 g1(HID / 128, MM / 128);
        gemm128_kernel<<<g1, 256>>>(tA, ff_w1 + (size_t)k * DD * HID,
                                    ff_b1 + (size_t)k * HID, nullptr, hid,
                                    MM, HID, DD, 1);
        dim3 g2(DD / 64, MM / 64);
        gemm64_kernel<<<g2, 256>>>(hid, ff_w2 + (size_t)k * HID * DD,
                                   ff_b2 + (size_t)k * DD, x, x, MM, DD, HID, 0);
    };

    for (int it = 0; it < NITER; it++) {
        // self blocks
        run_ln(L, ln_g + 0 * DD, ln_b + 0 * DD, tA);
        run_attn(0, tA, tA, L);
        run_ff(0, L);

        run_ln(Nb, ln_g + 1 * DD, ln_b + 1 * DD, tA);
        run_attn(1, tA, tA, Nb);
        run_ff(1, Nb);

        run_ln(O, ln_g + 2 * DD, ln_b + 2 * DD, tA);
        run_attn(2, tA, tA, O);
        run_ff(2, O);

        // cross blocks: tO = ln3(O) persists in tB across both
        run_ln(O, ln_g + 3 * DD, ln_b + 3 * DD, tB);

        run_ln(L, ln_g + 4 * DD, ln_b + 4 * DD, tC);
        run_attn(3, tC, tB, L);
        run_ff(3, L);

        run_ln(Nb, ln_g + 5 * DD, ln_b + 5 * DD, tC);
        run_attn(4, tC, tB, Nb);
        run_ff(4, Nb);

        // final O update: needs tL (tA), tN (tB), tO (tC) simultaneously
        run_ln(L,  ln_g + 6 * DD, ln_b + 6 * DD, tA);
        run_ln(Nb, ln_g + 7 * DD, ln_b + 7 * DD, tB);
        run_ln(O,  ln_g + 8 * DD, ln_b + 8 * DD, tC);
        run_attn(5, tC, tB, O);   // O += att(tO, tN, tN)
        run_attn(6, tC, tA, O);   // O += att(tO, tL, tL)
        run_ff(5, O);
    }
}

// round 2
// speedup vs baseline: 1.0023x; 1.0023x over previous
#include <cuda_runtime.h>
#include <math.h>

#define BB 2
#define SS 1024
#define DD 256
#define HH 4
#define CC 64
#define WINSZ 10
#define NITER 2
#define MM (BB*SS)          /* 2048 rows */
#define HID (8*DD)          /* 2048 */
#define BSD (BB*SS*DD)      /* 524288 */

// ---------------- scratch (static device globals; no allocation) ------------
__device__ float g_tmpA[BSD];
__device__ float g_tmpB[BSD];
__device__ float g_tmpC[BSD];
__device__ float g_Q[BSD];
__device__ float g_K[BSD];
__device__ float g_V[BSD];
__device__ float g_G[BSD];
__device__ float g_ctx[BSD];
__device__ float g_hid[(size_t)MM * HID];

// ---------------- LayerNorm: one block per row, 256 threads -----------------
__global__ void ln_kernel(const float* __restrict__ x, const float* __restrict__ g,
                          const float* __restrict__ b, float* __restrict__ out)
{
    int row = blockIdx.x;
    int t   = threadIdx.x;
    float v = x[(size_t)row * DD + t];

    __shared__ float red[8];
    __shared__ float mean_s, rstd_s;

    float s = v;
    #pragma unroll
    for (int o = 16; o > 0; o >>= 1) s += __shfl_xor_sync(0xffffffffu, s, o);
    if ((t & 31) == 0) red[t >> 5] = s;
    __syncthreads();
    if (t == 0) {
        float tot = 0.f;
        #pragma unroll
        for (int i = 0; i < 8; i++) tot += red[i];
        mean_s = tot * (1.0f / DD);
    }
    __syncthreads();
    float mean = mean_s;
    float d = v - mean;

    s = d * d;
    #pragma unroll
    for (int o = 16; o > 0; o >>= 1) s += __shfl_xor_sync(0xffffffffu, s, o);
    if ((t & 31) == 0) red[t >> 5] = s;
    __syncthreads();
    if (t == 0) {
        float tot = 0.f;
        #pragma unroll
        for (int i = 0; i < 8; i++) tot += red[i];
        rstd_s = rsqrtf(tot * (1.0f / DD) + 1e-5f);
    }
    __syncthreads();
    out[(size_t)row * DD + t] = d * rstd_s * g[t] + b[t];
}

// ---------------- generic tiled SGEMM body ----------------------------------
// C[M,N] = epilogue(A[M,K] @ B[K,N] + bias) (+ res). mode: 0=none 1=relu 2=sigmoid
template<int BM, int BN, int BK, int TM, int TN>
__device__ __forceinline__ void gemm_body(
    const float* __restrict__ A, const float* __restrict__ Bm,
    const float* __restrict__ bias, const float* __restrict__ res,
    float* __restrict__ Cm, int M, int N, int K, int mode)
{
    constexpr int TX = BN / TN;
    constexpr int TY = BM / TM;
    constexpr int THREADS = TX * TY;

    __shared__ float As[BK][BM + 4];
    __shared__ float Bs[BK][BN + 4];

    int tid = threadIdx.x;
    int tx  = tid % TX;
    int ty  = tid / TX;
    int row0 = blockIdx.y * BM;
    int col0 = blockIdx.x * BN;

    float acc[TM][TN];
    #pragma unroll
    for (int i = 0; i < TM; i++)
        #pragma unroll
        for (int j = 0; j < TN; j++) acc[i][j] = 0.f;

    for (int k0 = 0; k0 < K; k0 += BK) {
        #pragma unroll
        for (int i = tid; i < BM * BK; i += THREADS) {
            int r = i / BK, c = i % BK;
            As[c][r] = A[(size_t)(row0 + r) * K + k0 + c];
        }
        #pragma unroll
        for (int i = tid; i < BK * BN; i += THREADS) {
            int r = i / BN, c = i % BN;
            Bs[r][c] = Bm[(size_t)(k0 + r) * N + col0 + c];
        }
        __syncthreads();

        #pragma unroll
        for (int kk = 0; kk < BK; kk++) {
            float ra[TM], rb[TN];
            #pragma unroll
            for (int i = 0; i < TM; i++) ra[i] = As[kk][ty * TM + i];
            #pragma unroll
            for (int j = 0; j < TN; j++) rb[j] = Bs[kk][tx * TN + j];
            #pragma unroll
            for (int i = 0; i < TM; i++)
                #pragma unroll
                for (int j = 0; j < TN; j++)
                    acc[i][j] = fmaf(ra[i], rb[j], acc[i][j]);
        }
        __syncthreads();
    }

    #pragma unroll
    for (int i = 0; i < TM; i++) {
        int r = row0 + ty * TM + i;
        #pragma unroll
        for (int j = 0; j < TN; j++) {
            int c = col0 + tx * TN + j;
            float v = acc[i][j];
            if (bias) v += bias[c];
            if (mode == 1)      v = fmaxf(v, 0.f);
            else if (mode == 2) v = 1.f / (1.f + __expf(-v));
            if (res) v += res[(size_t)r * N + c];
            Cm[(size_t)r * N + c] = v;
        }
    }
}

__global__ void __launch_bounds__(256)
gemm64_kernel(const float* __restrict__ A, const float* __restrict__ Bm,
              const float* __restrict__ bias, const float* __restrict__ res,
              float* __restrict__ Cm, int M, int N, int K, int mode)
{
    gemm_body<64, 64, 16, 4, 4>(A, Bm, bias, res, Cm, M, N, K, mode);
}

__global__ void __launch_bounds__(256)
gemm128_kernel(const float* __restrict__ A, const float* __restrict__ Bm,
               const float* __restrict__ bias, const float* __restrict__ res,
               float* __restrict__ Cm, int M, int N, int K, int mode)
{
    gemm_body<128, 128, 16, 8, 8>(A, Bm, bias, res, Cm, M, N, K, mode);
}

// Fused Q/K/V/G projections: blockIdx.z selects which projection.
__global__ void __launch_bounds__(256)
qkvg_kernel(const float* __restrict__ xq, const float* __restrict__ xkv,
            const float* __restrict__ Wq, const float* __restrict__ Wk,
            const float* __restrict__ Wv, const float* __restrict__ Gw,
            const float* __restrict__ Gb)
{
    int z = blockIdx.z;
    const float* A    = (z == 0) ? xq : xkv;
    const float* W    = (z == 0) ? Wq : (z == 1) ? Wk : (z == 2) ? Wv : Gw;
    const float* bias = (z == 3) ? Gb : nullptr;
    float* C          = (z == 0) ? g_Q : (z == 1) ? g_K : (z == 2) ? g_V : g_G;
    int mode          = (z == 3) ? 2 : 0;
    gemm_body<64, 64, 16, 4, 4>(A, W, bias, nullptr, C, MM, DD, DD, mode);
}

// ---------------- windowed attention core: one warp per (n,h,s) -------------
// ctx[n,s,h*64+c] = (softmax_t(Q.K/8 with window+mask) @ V) * G
__global__ void __launch_bounds__(256)
attn_core_kernel(const unsigned char* __restrict__ mask)
{
    int idx  = blockIdx.x * blockDim.x + threadIdx.x;
    int gw   = idx >> 5;
    int lane = idx & 31;
    if (gw >= BB * HH * SS) return;

    int s = gw & (SS - 1);
    int h = (gw >> 10) & (HH - 1);
    int n = gw >> 12;

    int base_q = (n * SS + s) * DD + h * CC;
    float q0 = g_Q[base_q + lane];
    float q1 = g_Q[base_q + 32 + lane];

    int t0 = s - WINSZ; if (t0 < 0) t0 = 0;
    int t1 = s + WINSZ; if (t1 > SS - 1) t1 = SS - 1;
    int cnt = t1 - t0 + 1;

    float sc[2 * WINSZ + 1];
    float mx = -1e30f;
    for (int i = 0; i < cnt; i++) {
        int t = t0 + i;
        float v;
        if (mask[n * SS + t]) {
            v = -1e30f;
        } else {
            int bk = (n * SS + t) * DD + h * CC;
            float p = q0 * g_K[bk + lane] + q1 * g_K[bk + 32 + lane];
            #pragma unroll
            for (int o = 16; o > 0; o >>= 1) p += __shfl_xor_sync(0xffffffffu, p, o);
            v = p * 0.125f;
        }
        sc[i] = v;
        mx = fmaxf(mx, v);
    }

    float denom = 0.f;
    for (int i = 0; i < cnt; i++) {
        float e = (sc[i] <= -1e29f) ? 0.f : __expf(sc[i] - mx);
        sc[i] = e;
        denom += e;
    }
    float inv = (denom > 0.f) ? (1.f / denom) : 0.f;

    float o0 = 0.f, o1 = 0.f;
    for (int i = 0; i < cnt; i++) {
        int bv = (n * SS + (t0 + i)) * DD + h * CC;
        float a = sc[i] * inv;
        o0 = fmaf(a, g_V[bv + lane], o0);
        o1 = fmaf(a, g_V[bv + 32 + lane], o1);
    }
    g_ctx[base_q + lane]      = o0 * g_G[base_q + lane];
    g_ctx[base_q + 32 + lane] = o1 * g_G[base_q + 32 + lane];
}

// ---------------- host orchestration ----------------------------------------
extern "C" void kernel_launch(void* const* d_in, const int* in_sizes, int n_in,
                              void* d_out, int out_size)
{
    (void)in_sizes; (void)n_in; (void)out_size;

    const float* inL = (const float*)d_in[0];
    const float* inN = (const float*)d_in[1];
    const float* inO = (const float*)d_in[2];
    const unsigned char* mask = (const unsigned char*)d_in[3];
    const float* aWq = (const float*)d_in[4];
    const float* aWk = (const float*)d_in[5];
    const float* aWv = (const float*)d_in[6];
    const float* aGw = (const float*)d_in[7];
    const float* aGb = (const float*)d_in[8];
    const float* aOw = (const float*)d_in[9];
    const float* aOb = (const float*)d_in[10];
    const float* ln_g = (const float*)d_in[11];
    const float* ln_b = (const float*)d_in[12];
    const float* ff_g = (const float*)d_in[13];
    const float* ff_b = (const float*)d_in[14];
    const float* ff_w1 = (const float*)d_in[15];
    const float* ff_b1 = (const float*)d_in[16];
    const float* ff_w2 = (const float*)d_in[17];
    const float* ff_b2 = (const float*)d_in[18];

    float* L  = (float*)d_out;
    float* Nb = L + BSD;
    float* O  = Nb + BSD;

    cudaMemcpyAsync(L,  inL, (size_t)BSD * sizeof(float), cudaMemcpyDeviceToDevice);
    cudaMemcpyAsync(Nb, inN, (size_t)BSD * sizeof(float), cudaMemcpyDeviceToDevice);
    cudaMemcpyAsync(O,  inO, (size_t)BSD * sizeof(float), cudaMemcpyDeviceToDevice);

    void *p_tA, *p_tB, *p_tC, *p_ctx, *p_hid;
    cudaGetSymbolAddress(&p_tA,  g_tmpA);
    cudaGetSymbolAddress(&p_tB,  g_tmpB);
    cudaGetSymbolAddress(&p_tC,  g_tmpC);
    cudaGetSymbolAddress(&p_ctx, g_ctx);
    cudaGetSymbolAddress(&p_hid, g_hid);
    float* tA  = (float*)p_tA;
    float* tB  = (float*)p_tB;
    float* tC  = (float*)p_tC;
    float* ctx = (float*)p_ctx;
    float* hid = (float*)p_hid;

    auto run_ln = [&](const float* x, const float* g, const float* b, float* out) {
        ln_kernel<<<MM, DD>>>(x, g, b, out);
    };

    auto run_attn = [&](int k, const float* xq, const float* xkv, float* x) {
        dim3 gq(DD / 64, MM / 64, 4);
        qkvg_kernel<<<gq, 256>>>(xq, xkv,
                                 aWq + (size_t)k * DD * DD,
                                 aWk + (size_t)k * DD * DD,
                                 aWv + (size_t)k * DD * DD,
                                 aGw + (size_t)k * DD * DD,
                                 aGb + (size_t)k * DD);
        attn_core_kernel<<<(BB * HH * SS * 32) / 256, 256>>>(mask);
        dim3 gp(DD / 64, MM / 64);
        gemm64_kernel<<<gp, 256>>>(ctx, aOw + (size_t)k * DD * DD,
                                   aOb + (size_t)k * DD, x, x, MM, DD, DD, 0);
    };

    auto run_ff = [&](int k, float* x) {
        run_ln(x, ff_g + (size_t)k * DD, ff_b + (size_t)k * DD, tA);
        dim3 g1(HID / 128, MM / 128);
        gemm128_kernel<<<g1, 256>>>(tA, ff_w1 + (size_t)k * DD * HID,
                                    ff_b1 + (size_t)k * HID, nullptr, hid,
                                    MM, HID, DD, 1);
        dim3 g2(DD / 64, MM / 64);
        gemm64_kernel<<<g2, 256>>>(hid, ff_w2 + (size_t)k * HID * DD,
                                   ff_b2 + (size_t)k * DD, x, x, MM, DD, HID, 0);
    };

    for (int it = 0; it < NITER; it++) {
        // self blocks
        run_ln(L, ln_g + 0 * DD, ln_b + 0 * DD, tA);
        run_attn(0, tA, tA, L);
        run_ff(0, L);

        run_ln(Nb, ln_g + 1 * DD, ln_b + 1 * DD, tA);
        run_attn(1, tA, tA, Nb);
        run_ff(1, Nb);

        run_ln(O, ln_g + 2 * DD, ln_b + 2 * DD, tA);
        run_attn(2, tA, tA, O);
        run_ff(2, O);

        // cross blocks: tO = ln3(O) persists in tB across both
        run_ln(O, ln_g + 3 * DD, ln_b + 3 * DD, tB);

        run_ln(L, ln_g + 4 * DD, ln_b + 4 * DD, tC);
        run_attn(3, tC, tB, L);
        run_ff(3, L);

        run_ln(Nb, ln_g + 5 * DD, ln_b + 5 * DD, tC);
        run_attn(4, tC, tB, Nb);
        run_ff(4, Nb);

        // final O update: needs tL (tA), tN (tB), tO (tC) simultaneously
        run_ln(L,  ln_g + 6 * DD, ln_b + 6 * DD, tA);
        run_ln(Nb, ln_g + 7 * DD, ln_b + 7 * DD, tB);
        run_ln(O,  ln_g + 8 * DD, ln_b + 8 * DD, tC);
        run_attn(5, tC, tB, O);   // O += att(tO, tN, tN)
        run_attn(6, tC, tA, O);   // O += att(tO, tL, tL)
        run_ff(5, O);
    }
}

// round 3
// speedup vs baseline: 2.0838x; 2.0790x over previous
#include <cuda_runtime.h>
#include <cuda_bf16.h>
#include <stdint.h>
#include <math.h>

#define BB 2
#define SS 1024
#define DD 256
#define HH 4
#define CC 64
#define WINSZ 10
#define NITER 2
#define MM (BB*SS)          /* 2048 */
#define HID (8*DD)          /* 2048 */
#define BSD (BB*SS*DD)      /* 524288 */

typedef __nv_bfloat16 bf16;

// ---------------- scratch (device globals; no allocation) -------------------
__device__ float g_tmpA[BSD];
__device__ float g_tmpB[BSD];
__device__ float g_tmpC[BSD];
__device__ float g_Q[BSD];
__device__ float g_K[BSD];
__device__ float g_V[BSD];
__device__ float g_G[BSD];
__device__ float g_ctx[BSD];
__device__ float g_hid[(size_t)MM * HID];

// pre-split transposed weights: [N][K] bf16 hi / lo
__device__ bf16 g_WqTh[7*DD*DD], g_WqTl[7*DD*DD];
__device__ bf16 g_WkTh[7*DD*DD], g_WkTl[7*DD*DD];
__device__ bf16 g_WvTh[7*DD*DD], g_WvTl[7*DD*DD];
__device__ bf16 g_GwTh[7*DD*DD], g_GwTl[7*DD*DD];
__device__ bf16 g_OwTh[7*DD*DD], g_OwTl[7*DD*DD];
__device__ bf16 g_w1Th[(size_t)6*DD*HID], g_w1Tl[(size_t)6*DD*HID];
__device__ bf16 g_w2Th[(size_t)6*HID*DD], g_w2Tl[(size_t)6*HID*DD];

__device__ __forceinline__ void split2(float v, bf16& h, bf16& l){
    h = __float2bfloat16(v);
    l = __float2bfloat16(v - __bfloat162float(h));
}

// ---------------- weight transpose + split: W[K,N] -> Th/Tl[N,K] ------------
__global__ void __launch_bounds__(256) wsplit_kernel(
    const float* __restrict__ W, bf16* __restrict__ Th, bf16* __restrict__ Tl,
    int K, int N)
{
    const float* w = W + (size_t)blockIdx.z * K * N;
    bf16* th = Th + (size_t)blockIdx.z * K * N;
    bf16* tl = Tl + (size_t)blockIdx.z * K * N;
    __shared__ float sm[32][33];
    int n0 = blockIdx.x * 32, k0 = blockIdx.y * 32;
    int tx = threadIdx.x & 31, ty = threadIdx.x >> 5;
    #pragma unroll
    for (int i = 0; i < 4; i++)
        sm[ty + i*8][tx] = w[(size_t)(k0 + ty + i*8) * N + n0 + tx];
    __syncthreads();
    #pragma unroll
    for (int i = 0; i < 4; i++) {
        int n = n0 + ty + i*8;
        bf16 h, l; split2(sm[tx][ty + i*8], h, l);
        th[(size_t)n * K + k0 + tx] = h;
        tl[(size_t)n * K + k0 + tx] = l;
    }
}

// ---------------- LayerNorm ------------------------------------------------
__global__ void ln_kernel(const float* __restrict__ x, const float* __restrict__ g,
                          const float* __restrict__ b, float* __restrict__ out)
{
    int row = blockIdx.x;
    int t   = threadIdx.x;
    float v = x[(size_t)row * DD + t];
    __shared__ float red[8];
    __shared__ float mean_s, rstd_s;
    float s = v;
    #pragma unroll
    for (int o = 16; o > 0; o >>= 1) s += __shfl_xor_sync(0xffffffffu, s, o);
    if ((t & 31) == 0) red[t >> 5] = s;
    __syncthreads();
    if (t == 0) { float tot=0.f; for (int i=0;i<8;i++) tot+=red[i]; mean_s = tot*(1.0f/DD); }
    __syncthreads();
    float d = v - mean_s;
    s = d * d;
    #pragma unroll
    for (int o = 16; o > 0; o >>= 1) s += __shfl_xor_sync(0xffffffffu, s, o);
    if ((t & 31) == 0) red[t >> 5] = s;
    __syncthreads();
    if (t == 0) { float tot=0.f; for (int i=0;i<8;i++) tot+=red[i]; rstd_s = rsqrtf(tot*(1.0f/DD)+1e-5f); }
    __syncthreads();
    out[(size_t)row * DD + t] = d * rstd_s * g[t] + b[t];
}

// ---------------- bf16 split-compensated MMA GEMM ---------------------------
// C[M,N] = epi(A[M,K](f32) @ W[K,N] + bias) (+res), W given split as Bh/Bl [N,K]
#define LDSB 40   /* 32 + 8 pad halves */

__device__ __forceinline__ void mma16816(float* c, const uint32_t* a, const uint32_t* b){
    asm volatile("mma.sync.aligned.m16n8k16.row.col.f32.bf16.bf16.f32 "
        "{%0,%1,%2,%3}, {%4,%5,%6,%7}, {%8,%9}, {%0,%1,%2,%3};"
        : "+f"(c[0]), "+f"(c[1]), "+f"(c[2]), "+f"(c[3])
        : "r"(a[0]), "r"(a[1]), "r"(a[2]), "r"(a[3]), "r"(b[0]), "r"(b[1]));
}

__device__ void gemm_mma_body(const float* __restrict__ A,
    const bf16* __restrict__ Bh, const bf16* __restrict__ Bl,
    const float* __restrict__ bias, const float* __restrict__ res,
    float* __restrict__ C, int M, int N, int K, int mode)
{
    __shared__ __align__(16) bf16 Ash[128][LDSB], Asl[128][LDSB];
    __shared__ __align__(16) bf16 Bsh[128][LDSB], Bsl[128][LDSB];

    int tid  = threadIdx.x;
    int warp = tid >> 5, lane = tid & 31;
    int wm = warp >> 2, wn = warp & 3;            // 2 x 4 warps
    int row0 = blockIdx.y * 128, col0 = blockIdx.x * 128;
    int g = lane >> 2, tig = lane & 3;

    float acc[4][4][4];
    #pragma unroll
    for (int i=0;i<4;i++) for (int j=0;j<4;j++) for (int q=0;q<4;q++) acc[i][j][q]=0.f;

    for (int k0 = 0; k0 < K; k0 += 32) {
        // stage A (fp32 -> bf16 hi/lo)
        #pragma unroll
        for (int p = 0; p < 4; p++) {
            int r = p*32 + (tid >> 3);
            int c = (tid & 7) * 4;
            float4 v = *(const float4*)&A[(size_t)(row0 + r) * K + k0 + c];
            bf16 h0,l0,h1,l1,h2,l2,h3,l3;
            split2(v.x,h0,l0); split2(v.y,h1,l1); split2(v.z,h2,l2); split2(v.w,h3,l3);
            *(__nv_bfloat162*)&Ash[r][c]   = __halves2bfloat162(h0,h1);
            *(__nv_bfloat162*)&Ash[r][c+2] = __halves2bfloat162(h2,h3);
            *(__nv_bfloat162*)&Asl[r][c]   = __halves2bfloat162(l0,l1);
            *(__nv_bfloat162*)&Asl[r][c+2] = __halves2bfloat162(l2,l3);
        }
        // stage B (pre-split, [N,K])
        #pragma unroll
        for (int p = 0; p < 2; p++) {
            int slot = tid + 256*p;
            int r = slot >> 2, cq = (slot & 3) * 8;
            *(uint4*)&Bsh[r][cq] = *(const uint4*)&Bh[(size_t)(col0 + r) * K + k0 + cq];
            *(uint4*)&Bsl[r][cq] = *(const uint4*)&Bl[(size_t)(col0 + r) * K + k0 + cq];
        }
        __syncthreads();

        #pragma unroll
        for (int kk = 0; kk < 2; kk++) {
            int kb = kk * 16 + tig * 2;
            uint32_t ah[4][4], al[4][4], bh[4][2], bl[4][2];
            #pragma unroll
            for (int mi = 0; mi < 4; mi++) {
                int r = wm*64 + mi*16 + g;
                ah[mi][0] = *(const uint32_t*)&Ash[r  ][kb];
                ah[mi][1] = *(const uint32_t*)&Ash[r+8][kb];
                ah[mi][2] = *(const uint32_t*)&Ash[r  ][kb+8];
                ah[mi][3] = *(const uint32_t*)&Ash[r+8][kb+8];
                al[mi][0] = *(const uint32_t*)&Asl[r  ][kb];
                al[mi][1] = *(const uint32_t*)&Asl[r+8][kb];
                al[mi][2] = *(const uint32_t*)&Asl[r  ][kb+8];
                al[mi][3] = *(const uint32_t*)&Asl[r+8][kb+8];
            }
            #pragma unroll
            for (int ni = 0; ni < 4; ni++) {
                int n = wn*32 + ni*8 + g;
                bh[ni][0] = *(const uint32_t*)&Bsh[n][kb];
                bh[ni][1] = *(const uint32_t*)&Bsh[n][kb+8];
                bl[ni][0] = *(const uint32_t*)&Bsl[n][kb];
                bl[ni][1] = *(const uint32_t*)&Bsl[n][kb+8];
            }
            #pragma unroll
            for (int mi = 0; mi < 4; mi++)
                #pragma unroll
                for (int ni = 0; ni < 4; ni++) {
                    mma16816(acc[mi][ni], ah[mi], bh[ni]);
                    mma16816(acc[mi][ni], ah[mi], bl[ni]);
                    mma16816(acc[mi][ni], al[mi], bh[ni]);
                }
        }
        __syncthreads();
    }

    // epilogue
    #pragma unroll
    for (int mi = 0; mi < 4; mi++) {
        #pragma unroll
        for (int ni = 0; ni < 4; ni++) {
            int r1 = row0 + wm*64 + mi*16 + g;
            int c1 = col0 + wn*32 + ni*8 + tig*2;
            #pragma unroll
            for (int q = 0; q < 4; q++) {
                int r = (q < 2) ? r1 : r1 + 8;
                int c = c1 + (q & 1);
                float v = acc[mi][ni][q];
                if (bias) v += bias[c];
                if (mode == 1)      v = fmaxf(v, 0.f);
                else if (mode == 2) v = 1.f / (1.f + __expf(-v));
                if (res) v += res[(size_t)r * N + c];
                C[(size_t)r * N + c] = v;
            }
        }
    }
}

__global__ void __launch_bounds__(256,2)
gemm_mma_kernel(const float* __restrict__ A, const bf16* __restrict__ Bh,
                const bf16* __restrict__ Bl, const float* __restrict__ bias,
                const float* __restrict__ res, float* __restrict__ C,
                int M, int N, int K, int mode)
{
    gemm_mma_body(A, Bh, Bl, bias, res, C, M, N, K, mode);
}

// QKVG fused: z selects projection; weights from device globals at module k.
__global__ void __launch_bounds__(256,2)
qkvg_mma_kernel(const float* __restrict__ xq, const float* __restrict__ xkv,
                int k, const float* __restrict__ aGb)
{
    int z = blockIdx.z;
    size_t off = (size_t)k * DD * DD;
    const float* A = (z == 0) ? xq : xkv;
    const bf16 *bh, *bl; float* C; const float* bias = nullptr; int mode = 0;
    if      (z == 0) { bh = g_WqTh + off; bl = g_WqTl + off; C = g_Q; }
    else if (z == 1) { bh = g_WkTh + off; bl = g_WkTl + off; C = g_K; }
    else if (z == 2) { bh = g_WvTh + off; bl = g_WvTl + off; C = g_V; }
    else             { bh = g_GwTh + off; bl = g_GwTl + off; C = g_G;
                       bias = aGb + (size_t)k * DD; mode = 2; }
    gemm_mma_body(A, bh, bl, bias, nullptr, C, MM, DD, DD, mode);
}

// ---------------- windowed attention core: one warp per (n,h,s) -------------
__global__ void __launch_bounds__(256)
attn_core_kernel(const unsigned char* __restrict__ mask)
{
    int idx  = blockIdx.x * blockDim.x + threadIdx.x;
    int gw   = idx >> 5;
    int lane = idx & 31;
    if (gw >= BB * HH * SS) return;
    int s = gw & (SS - 1);
    int h = (gw >> 10) & (HH - 1);
    int n = gw >> 12;

    int base_q = (n * SS + s) * DD + h * CC;
    float q0 = g_Q[base_q + lane];
    float q1 = g_Q[base_q + 32 + lane];

    int t0 = s - WINSZ; if (t0 < 0) t0 = 0;
    int t1 = s + WINSZ; if (t1 > SS - 1) t1 = SS - 1;
    int cnt = t1 - t0 + 1;

    float sc[2 * WINSZ + 1];
    float mx = -1e30f;
    for (int i = 0; i < cnt; i++) {
        int t = t0 + i;
        float v;
        if (mask[n * SS + t]) v = -1e30f;
        else {
            int bk = (n * SS + t) * DD + h * CC;
            float p = q0 * g_K[bk + lane] + q1 * g_K[bk + 32 + lane];
            #pragma unroll
            for (int o = 16; o > 0; o >>= 1) p += __shfl_xor_sync(0xffffffffu, p, o);
            v = p * 0.125f;
        }
        sc[i] = v;
        mx = fmaxf(mx, v);
    }
    float denom = 0.f;
    for (int i = 0; i < cnt; i++) {
        float e = (sc[i] <= -1e29f) ? 0.f : __expf(sc[i] - mx);
        sc[i] = e; denom += e;
    }
    float inv = (denom > 0.f) ? (1.f / denom) : 0.f;
    float o0 = 0.f, o1 = 0.f;
    for (int i = 0; i < cnt; i++) {
        int bv = (n * SS + (t0 + i)) * DD + h * CC;
        float a = sc[i] * inv;
        o0 = fmaf(a, g_V[bv + lane], o0);
        o1 = fmaf(a, g_V[bv + 32 + lane], o1);
    }
    g_ctx[base_q + lane]      = o0 * g_G[base_q + lane];
    g_ctx[base_q + 32 + lane] = o1 * g_G[base_q + 32 + lane];
}

// ---------------- host orchestration ----------------------------------------
extern "C" void kernel_launch(void* const* d_in, const int* in_sizes, int n_in,
                              void* d_out, int out_size)
{
    (void)in_sizes; (void)n_in; (void)out_size;
    const float* inL = (const float*)d_in[0];
    const float* inN = (const float*)d_in[1];
    const float* inO = (const float*)d_in[2];
    const unsigned char* mask = (const unsigned char*)d_in[3];
    const float* aWq = (const float*)d_in[4];
    const float* aWk = (const float*)d_in[5];
    const float* aWv = (const float*)d_in[6];
    const float* aGw = (const float*)d_in[7];
    const float* aGb = (const float*)d_in[8];
    const float* aOw = (const float*)d_in[9];
    const float* aOb = (const float*)d_in[10];
    const float* ln_g = (const float*)d_in[11];
    const float* ln_b = (const float*)d_in[12];
    const float* ff_g = (const float*)d_in[13];
    const float* ff_b = (const float*)d_in[14];
    const float* ff_w1 = (const float*)d_in[15];
    const float* ff_b1 = (const float*)d_in[16];
    const float* ff_w2 = (const float*)d_in[17];
    const float* ff_b2 = (const float*)d_in[18];

    float* L  = (float*)d_out;
    float* Nb = L + BSD;
    float* O  = Nb + BSD;

    cudaMemcpyAsync(L,  inL, (size_t)BSD * sizeof(float), cudaMemcpyDeviceToDevice);
    cudaMemcpyAsync(Nb, inN, (size_t)BSD * sizeof(float), cudaMemcpyDeviceToDevice);
    cudaMemcpyAsync(O,  inO, (size_t)BSD * sizeof(float), cudaMemcpyDeviceToDevice);

    void *pa;
    #define SYM(var, sym) cudaGetSymbolAddress(&pa, sym); auto var = (decltype(&sym[0]))pa;
    SYM(tA, g_tmpA) SYM(tB, g_tmpB) SYM(tC, g_tmpC)
    SYM(ctx, g_ctx) SYM(hid, g_hid)
    SYM(wqh, g_WqTh) SYM(wql, g_WqTl) SYM(wkh, g_WkTh) SYM(wkl, g_WkTl)
    SYM(wvh, g_WvTh) SYM(wvl, g_WvTl) SYM(gwh, g_GwTh) SYM(gwl, g_GwTl)
    SYM(owh, g_OwTh) SYM(owl, g_OwTl)
    SYM(w1h, g_w1Th) SYM(w1l, g_w1Tl) SYM(w2h, g_w2Th) SYM(w2l, g_w2Tl)
    #undef SYM

    // split + transpose all weights
    {
        dim3 gA(DD/32, DD/32, 7);
        wsplit_kernel<<<gA, 256>>>(aWq, wqh, wql, DD, DD);
        wsplit_kernel<<<gA, 256>>>(aWk, wkh, wkl, DD, DD);
        wsplit_kernel<<<gA, 256>>>(aWv, wvh, wvl, DD, DD);
        wsplit_kernel<<<gA, 256>>>(aGw, gwh, gwl, DD, DD);
        wsplit_kernel<<<gA, 256>>>(aOw, owh, owl, DD, DD);
        dim3 g1(HID/32, DD/32, 6);
        wsplit_kernel<<<g1, 256>>>(ff_w1, w1h, w1l, DD, HID);
        dim3 g2(DD/32, HID/32, 6);
        wsplit_kernel<<<g2, 256>>>(ff_w2, w2h, w2l, HID, DD);
    }

    auto run_ln = [&](const float* x, int k, const float* gg, const float* bb, float* out) {
        ln_kernel<<<MM, DD>>>(x, gg + (size_t)k*DD, bb + (size_t)k*DD, out);
    };
    auto run_attn = [&](int k, const float* xq, const float* xkv, float* x) {
        dim3 gq(DD/128, MM/128, 4);
        qkvg_mma_kernel<<<gq, 256>>>(xq, xkv, k, aGb);
        attn_core_kernel<<<(BB*HH*SS*32)/256, 256>>>(mask);
        dim3 gp(DD/128, MM/128);
        gemm_mma_kernel<<<gp, 256>>>(ctx, owh + (size_t)k*DD*DD, owl + (size_t)k*DD*DD,
                                     aOb + (size_t)k*DD, x, x, MM, DD, DD, 0);
    };
    auto run_ff = [&](int k, float* x) {
        run_ln(x, k, ff_g, ff_b, tA);
        dim3 g1(HID/128, MM/128);
        gemm_mma_kernel<<<g1, 256>>>(tA, w1h + (size_t)k*DD*HID, w1l + (size_t)k*DD*HID,
                                     ff_b1 + (size_t)k*HID, nullptr, hid, MM, HID, DD, 1);
        dim3 g2(DD/128, MM/128);
        gemm_mma_kernel<<<g2, 256>>>(hid, w2h + (size_t)k*HID*DD, w2l + (size_t)k*HID*DD,
                                     ff_b2 + (size_t)k*DD, x, x, MM, DD, HID, 0);
    };

    for (int it = 0; it < NITER; it++) {
        run_ln(L, 0, ln_g, ln_b, tA);  run_attn(0, tA, tA, L);  run_ff(0, L);
        run_ln(Nb, 1, ln_g, ln_b, tA); run_attn(1, tA, tA, Nb); run_ff(1, Nb);
        run_ln(O, 2, ln_g, ln_b, tA);  run_attn(2, tA, tA, O);  run_ff(2, O);

        run_ln(O, 3, ln_g, ln_b, tB);                 // tO (shared by both cross blocks)
        run_ln(L, 4, ln_g, ln_b, tC);  run_attn(3, tC, tB, L);  run_ff(3, L);
        run_ln(Nb, 5, ln_g, ln_b, tC); run_attn(4, tC, tB, Nb); run_ff(4, Nb);

        run_ln(L, 6, ln_g, ln_b, tA);                 // tL
        run_ln(Nb, 7, ln_g, ln_b, tB);                // tN
        run_ln(O, 8, ln_g, ln_b, tC);                 // tO
        run_attn(5, tC, tB, O);
        run_attn(6, tC, tA, O);
        run_ff(5, O);
    }
}

// round 4
// speedup vs baseline: 2.8307x; 1.3584x over previous
#include <cuda_runtime.h>
#include <cuda_bf16.h>
#include <stdint.h>
#include <math.h>

#define BB 2
#define SS 1024
#define DD 256
#define HH 4
#define CC 64
#define WINSZ 10
#define NITER 2
#define MM 2048
#define HID 2048
#define BSD (BB*SS*DD)
#define MH ((size_t)MM*HID)

typedef __nv_bfloat16 bf16;

// ---------------- scratch (device globals; no allocation) -------------------
__device__ float g_tmpA[BSD], g_tmpB[BSD], g_tmpC[BSD], g_tmpD[BSD];
__device__ float g_Q[3*BSD], g_Kb[3*BSD], g_Vb[3*BSD], g_Gb[3*BSD];
__device__ float g_ctx[3*BSD];
__device__ float g_hid[3*MH];
__device__ float g_b56[DD];

// pre-split transposed weights: [N][K] bf16 hi / lo
__device__ bf16 g_WqTh[7*DD*DD], g_WqTl[7*DD*DD];
__device__ bf16 g_WkTh[7*DD*DD], g_WkTl[7*DD*DD];
__device__ bf16 g_WvTh[7*DD*DD], g_WvTl[7*DD*DD];
__device__ bf16 g_GwTh[7*DD*DD], g_GwTl[7*DD*DD];
__device__ bf16 g_OwTh[7*DD*DD], g_OwTl[7*DD*DD];
__device__ bf16 g_w1Th[(size_t)6*DD*HID], g_w1Tl[(size_t)6*DD*HID];
__device__ bf16 g_w2Th[(size_t)6*HID*DD], g_w2Tl[(size_t)6*HID*DD];
__device__ bf16 g_W56h[DD*512], g_W56l[DD*512];

__device__ __forceinline__ void split2(float v, bf16& h, bf16& l){
    h = __float2bfloat16(v);
    l = __float2bfloat16(v - __bfloat162float(h));
}

__device__ __forceinline__ uint32_t smem_u32(const void* p){
    uint32_t a;
    asm("{ .reg .u64 t; cvta.to.shared.u64 t, %1; cvt.u32.u64 %0, t; }" : "=r"(a) : "l"(p));
    return a;
}
__device__ __forceinline__ void cp16(uint32_t saddr, const void* g){
    asm volatile("cp.async.cg.shared.global [%0], [%1], 16;" :: "r"(saddr), "l"(g));
}

// ---------------- weight transpose + split: W[K,N] -> Th/Tl[N][ldt] ---------
__global__ void __launch_bounds__(256) wsplit_kernel(
    const float* __restrict__ W, bf16* __restrict__ Th, bf16* __restrict__ Tl,
    int K, int N, int ldt, int ooff, long long wstride, long long tstride)
{
    const float* w = W + (size_t)blockIdx.z * wstride;
    bf16* th = Th + (size_t)blockIdx.z * tstride;
    bf16* tl = Tl + (size_t)blockIdx.z * tstride;
    __shared__ float sm[32][33];
    int n0 = blockIdx.x * 32, k0 = blockIdx.y * 32;
    int tx = threadIdx.x & 31, ty = threadIdx.x >> 5;
    #pragma unroll
    for (int i = 0; i < 4; i++)
        sm[ty + i*8][tx] = w[(size_t)(k0 + ty + i*8) * N + n0 + tx];
    __syncthreads();
    #pragma unroll
    for (int i = 0; i < 4; i++) {
        int n = n0 + ty + i*8;
        bf16 h, l; split2(sm[tx][ty + i*8], h, l);
        th[(size_t)n * ldt + ooff + k0 + tx] = h;
        tl[(size_t)n * ldt + ooff + k0 + tx] = l;
    }
}

__global__ void b56_kernel(const float* __restrict__ aOb){
    int t = threadIdx.x;
    g_b56[t] = aOb[5*DD + t] + aOb[6*DD + t];
}

// ---------------- LayerNorm (batched over z) --------------------------------
struct LnS { const float* x; const float* g; const float* b; float* out; };
struct LnBatch { LnS s[3]; };

__global__ void __launch_bounds__(256) ln_kernel(LnBatch lb)
{
    LnS sl = lb.s[blockIdx.y];
    int row = blockIdx.x;
    int t   = threadIdx.x;
    float v = sl.x[(size_t)row * DD + t];
    __shared__ float red[8];
    __shared__ float mean_s, rstd_s;
    float s = v;
    #pragma unroll
    for (int o = 16; o > 0; o >>= 1) s += __shfl_xor_sync(0xffffffffu, s, o);
    if ((t & 31) == 0) red[t >> 5] = s;
    __syncthreads();
    if (t == 0) { float tot=0.f; for (int i=0;i<8;i++) tot+=red[i]; mean_s = tot*(1.0f/DD); }
    __syncthreads();
    float d = v - mean_s;
    s = d * d;
    #pragma unroll
    for (int o = 16; o > 0; o >>= 1) s += __shfl_xor_sync(0xffffffffu, s, o);
    if ((t & 31) == 0) red[t >> 5] = s;
    __syncthreads();
    if (t == 0) { float tot=0.f; for (int i=0;i<8;i++) tot+=red[i]; rstd_s = rsqrtf(tot*(1.0f/DD)+1e-5f); }
    __syncthreads();
    sl.out[(size_t)row * DD + t] = d * rstd_s * sl.g[t] + sl.b[t];
}

// ---------------- batched split-compensated MMA GEMM ------------------------
// slice: C[M,N] = epi(concat_k(A,A2)[M,K] @ Wsplit[K,N] + bias) (+res)
struct Slice {
    const float* A; const float* A2;
    const bf16* Bh; const bf16* Bl;
    const float* bias; const float* res; float* C;
    int mode;  // 0 none, 1 relu, 2 sigmoid
};
struct Batch { Slice s[12]; };

#define LDSB 40
#define TILEH (128*LDSB)

__device__ __forceinline__ void mma16816(float* c, const uint32_t* a, const uint32_t* b){
    asm volatile("mma.sync.aligned.m16n8k16.row.col.f32.bf16.bf16.f32 "
        "{%0,%1,%2,%3}, {%4,%5,%6,%7}, {%8,%9}, {%0,%1,%2,%3};"
        : "+f"(c[0]), "+f"(c[1]), "+f"(c[2]), "+f"(c[3])
        : "r"(a[0]), "r"(a[1]), "r"(a[2]), "r"(a[3]), "r"(b[0]), "r"(b[1]));
}

__global__ void __launch_bounds__(256,2)
gemm_batched(Batch bt, int M, int N, int K)
{
    extern __shared__ bf16 smraw[];
    bf16* Ash = smraw;
    bf16* Asl = Ash + 2*TILEH;
    bf16* Bsh = Asl + 2*TILEH;
    bf16* Bsl = Bsh + 2*TILEH;

    const Slice sl = bt.s[blockIdx.z];
    const int tid  = threadIdx.x;
    const int warp = tid >> 5, lane = tid & 31;
    const int wm = warp >> 2, wn = warp & 3;
    const int row0 = blockIdx.y * 128, col0 = blockIdx.x * 128;
    const int g8 = lane >> 2, tig = lane & 3;
    const int lda = sl.A2 ? 256 : K;

    const uint32_t sb_bh = smem_u32(Bsh);
    const uint32_t sb_bl = smem_u32(Bsl);

    float acc[4][4][4];
    #pragma unroll
    for (int i=0;i<4;i++) for (int j=0;j<4;j++) for (int q=0;q<4;q++) acc[i][j][q]=0.f;

    float4 va[4];
    auto loadA = [&](int kk){
        const float* Ap = sl.A; int kl = kk;
        if (sl.A2 && kk >= 256) { Ap = sl.A2; kl = kk - 256; }
        #pragma unroll
        for (int p=0;p<4;p++){
            int r = p*32 + (tid >> 3);
            int c = (tid & 7) * 4;
            va[p] = *(const float4*)&Ap[(size_t)(row0 + r) * lda + kl + c];
        }
    };
    auto storeA = [&](int st){
        #pragma unroll
        for (int p=0;p<4;p++){
            int r = p*32 + (tid >> 3);
            int c = (tid & 7) * 4;
            bf16 h0,l0,h1,l1,h2,l2,h3,l3;
            split2(va[p].x,h0,l0); split2(va[p].y,h1,l1);
            split2(va[p].z,h2,l2); split2(va[p].w,h3,l3);
            bf16* ah = &Ash[st*TILEH + r*LDSB + c];
            bf16* al = &Asl[st*TILEH + r*LDSB + c];
            *(__nv_bfloat162*)ah     = __halves2bfloat162(h0,h1);
            *(__nv_bfloat162*)(ah+2) = __halves2bfloat162(h2,h3);
            *(__nv_bfloat162*)al     = __halves2bfloat162(l0,l1);
            *(__nv_bfloat162*)(al+2) = __halves2bfloat162(l2,l3);
        }
    };
    auto cpB = [&](int kk, int st){
        #pragma unroll
        for (int p=0;p<2;p++){
            int slot = tid + 256*p;
            int r = slot >> 2, cq = (slot & 3) * 8;
            size_t go = (size_t)(col0 + r) * K + kk + cq;
            uint32_t so = (uint32_t)((st*TILEH + r*LDSB + cq) * 2);
            cp16(sb_bh + so, sl.Bh + go);
            cp16(sb_bl + so, sl.Bl + go);
        }
        asm volatile("cp.async.commit_group;" ::: "memory");
    };

    // prologue
    loadA(0);
    cpB(0, 0);
    storeA(0);
    asm volatile("cp.async.wait_group 0;" ::: "memory");
    __syncthreads();

    int st = 0;
    for (int k0 = 0; k0 < K; k0 += 32) {
        int nst = st ^ 1;
        bool more = (k0 + 32 < K);
        if (more) { loadA(k0 + 32); cpB(k0 + 32, nst); }

        #pragma unroll
        for (int kk = 0; kk < 2; kk++) {
            int kb = kk*16 + tig*2;
            uint32_t bh[4][2], bl[4][2];
            #pragma unroll
            for (int ni = 0; ni < 4; ni++) {
                int n = wn*32 + ni*8 + g8;
                const bf16* pbh = &Bsh[st*TILEH + n*LDSB + kb];
                const bf16* pbl = &Bsl[st*TILEH + n*LDSB + kb];
                bh[ni][0] = *(const uint32_t*)pbh;
                bh[ni][1] = *(const uint32_t*)(pbh+8);
                bl[ni][0] = *(const uint32_t*)pbl;
                bl[ni][1] = *(const uint32_t*)(pbl+8);
            }
            #pragma unroll
            for (int mi = 0; mi < 4; mi++) {
                int r = wm*64 + mi*16 + g8;
                const bf16* pah = &Ash[st*TILEH + r*LDSB + kb];
                const bf16* pal = &Asl[st*TILEH + r*LDSB + kb];
                uint32_t ah[4], al[4];
                ah[0] = *(const uint32_t*)pah;
                ah[1] = *(const uint32_t*)(pah + 8*LDSB);
                ah[2] = *(const uint32_t*)(pah + 8);
                ah[3] = *(const uint32_t*)(pah + 8*LDSB + 8);
                al[0] = *(const uint32_t*)pal;
                al[1] = *(const uint32_t*)(pal + 8*LDSB);
                al[2] = *(const uint32_t*)(pal + 8);
                al[3] = *(const uint32_t*)(pal + 8*LDSB + 8);
                #pragma unroll
                for (int ni = 0; ni < 4; ni++) {
                    mma16816(acc[mi][ni], ah, bh[ni]);
                    mma16816(acc[mi][ni], ah, bl[ni]);
                    mma16816(acc[mi][ni], al, bh[ni]);
                }
            }
        }
        if (more) storeA(nst);
        asm volatile("cp.async.wait_group 0;" ::: "memory");
        __syncthreads();
        st = nst;
    }

    // epilogue
    #pragma unroll
    for (int mi = 0; mi < 4; mi++) {
        #pragma unroll
        for (int ni = 0; ni < 4; ni++) {
            int r1 = row0 + wm*64 + mi*16 + g8;
            int c1 = col0 + wn*32 + ni*8 + tig*2;
            #pragma unroll
            for (int q = 0; q < 4; q++) {
                int r = (q < 2) ? r1 : r1 + 8;
                int c = c1 + (q & 1);
                float v = acc[mi][ni][q];
                if (sl.bias) v += sl.bias[c];
                if (sl.mode == 1)      v = fmaxf(v, 0.f);
                else if (sl.mode == 2) v = 1.f / (1.f + __expf(-v));
                if (sl.res) v += sl.res[(size_t)r * N + c];
                sl.C[(size_t)r * N + c] = v;
            }
        }
    }
}

// ---------------- windowed attention core (batched over z) ------------------
struct AtS { const float* Q; const float* K; const float* V; const float* G; float* ctx; };
struct AtBatch { AtS s[3]; };

__global__ void __launch_bounds__(256)
attn_core_kernel(AtBatch ab, const unsigned char* __restrict__ mask)
{
    AtS sl = ab.s[blockIdx.y];
    int idx  = blockIdx.x * blockDim.x + threadIdx.x;
    int gw   = idx >> 5;
    int lane = idx & 31;
    int s = gw & (SS - 1);
    int h = (gw >> 10) & (HH - 1);
    int n = gw >> 12;

    int base_q = (n * SS + s) * DD + h * CC;
    float q0 = sl.Q[base_q + lane];
    float q1 = sl.Q[base_q + 32 + lane];

    int t0 = s - WINSZ; if (t0 < 0) t0 = 0;
    int t1 = s + WINSZ; if (t1 > SS - 1) t1 = SS - 1;
    int cnt = t1 - t0 + 1;

    float sc[2 * WINSZ + 1];
    float mx = -1e30f;
    for (int i = 0; i < cnt; i++) {
        int t = t0 + i;
        float v;
        if (mask[n * SS + t]) v = -1e30f;
        else {
            int bk = (n * SS + t) * DD + h * CC;
            float p = q0 * sl.K[bk + lane] + q1 * sl.K[bk + 32 + lane];
            #pragma unroll
            for (int o = 16; o > 0; o >>= 1) p += __shfl_xor_sync(0xffffffffu, p, o);
            v = p * 0.125f;
        }
        sc[i] = v;
        mx = fmaxf(mx, v);
    }
    float denom = 0.f;
    for (int i = 0; i < cnt; i++) {
        float e = (sc[i] <= -1e29f) ? 0.f : __expf(sc[i] - mx);
        sc[i] = e; denom += e;
    }
    float inv = (denom > 0.f) ? (1.f / denom) : 0.f;
    float o0 = 0.f, o1 = 0.f;
    for (int i = 0; i < cnt; i++) {
        int bv = (n * SS + (t0 + i)) * DD + h * CC;
        float a = sc[i] * inv;
        o0 = fmaf(a, sl.V[bv + lane], o0);
        o1 = fmaf(a, sl.V[bv + 32 + lane], o1);
    }
    sl.ctx[base_q + lane]      = o0 * sl.G[base_q + lane];
    sl.ctx[base_q + 32 + lane] = o1 * sl.G[base_q + 32 + lane];
}

// ---------------- host orchestration ----------------------------------------
extern "C" void kernel_launch(void* const* d_in, const int* in_sizes, int n_in,
                              void* d_out, int out_size)
{
    (void)in_sizes; (void)n_in; (void)out_size;
    const float* inL = (const float*)d_in[0];
    const float* inN = (const float*)d_in[1];
    const float* inO = (const float*)d_in[2];
    const unsigned char* mask = (const unsigned char*)d_in[3];
    const float* aWq = (const float*)d_in[4];
    const float* aWk = (const float*)d_in[5];
    const float* aWv = (const float*)d_in[6];
    const float* aGw = (const float*)d_in[7];
    const float* aGb = (const float*)d_in[8];
    const float* aOw = (const float*)d_in[9];
    const float* aOb = (const float*)d_in[10];
    const float* ln_g = (const float*)d_in[11];
    const float* ln_b = (const float*)d_in[12];
    const float* ff_g = (const float*)d_in[13];
    const float* ff_b = (const float*)d_in[14];
    const float* ff_w1 = (const float*)d_in[15];
    const float* ff_b1 = (const float*)d_in[16];
    const float* ff_w2 = (const float*)d_in[17];
    const float* ff_b2 = (const float*)d_in[18];

    float* L  = (float*)d_out;
    float* Nb = L + BSD;
    float* O  = Nb + BSD;
    float* X[3] = { L, Nb, O };

    cudaMemcpyAsync(L,  inL, (size_t)BSD * sizeof(float), cudaMemcpyDeviceToDevice);
    cudaMemcpyAsync(Nb, inN, (size_t)BSD * sizeof(float), cudaMemcpyDeviceToDevice);
    cudaMemcpyAsync(O,  inO, (size_t)BSD * sizeof(float), cudaMemcpyDeviceToDevice);

    void* pa;
    #define SYM(var, sym) cudaGetSymbolAddress(&pa, sym); auto var = (decltype(&sym[0]))pa;
    SYM(tA, g_tmpA) SYM(tB, g_tmpB) SYM(tC, g_tmpC) SYM(tD, g_tmpD)
    SYM(Qb, g_Q) SYM(Kb, g_Kb) SYM(Vb, g_Vb) SYM(Gg, g_Gb)
    SYM(ctx, g_ctx) SYM(hid, g_hid) SYM(b56, g_b56)
    SYM(wqh, g_WqTh) SYM(wql, g_WqTl) SYM(wkh, g_WkTh) SYM(wkl, g_WkTl)
    SYM(wvh, g_WvTh) SYM(wvl, g_WvTl) SYM(gwh, g_GwTh) SYM(gwl, g_GwTl)
    SYM(owh, g_OwTh) SYM(owl, g_OwTl)
    SYM(w1h, g_w1Th) SYM(w1l, g_w1Tl) SYM(w2h, g_w2Th) SYM(w2l, g_w2Tl)
    SYM(w56h, g_W56h) SYM(w56l, g_W56l)
    #undef SYM

    const int SMEMB = 8 * TILEH * 2;   // 81920 bytes
    cudaFuncSetAttribute(gemm_batched, cudaFuncAttributeMaxDynamicSharedMemorySize, SMEMB);

    // ---- weight prep ----
    {
        dim3 gA(DD/32, DD/32, 7);
        wsplit_kernel<<<gA, 256>>>(aWq, wqh, wql, DD, DD, DD, 0, DD*DD, DD*DD);
        wsplit_kernel<<<gA, 256>>>(aWk, wkh, wkl, DD, DD, DD, 0, DD*DD, DD*DD);
        wsplit_kernel<<<gA, 256>>>(aWv, wvh, wvl, DD, DD, DD, 0, DD*DD, DD*DD);
        wsplit_kernel<<<gA, 256>>>(aGw, gwh, gwl, DD, DD, DD, 0, DD*DD, DD*DD);
        wsplit_kernel<<<gA, 256>>>(aOw, owh, owl, DD, DD, DD, 0, DD*DD, DD*DD);
        dim3 g1(HID/32, DD/32, 6);
        wsplit_kernel<<<g1, 256>>>(ff_w1, w1h, w1l, DD, HID, DD, 0, (long long)DD*HID, (long long)DD*HID);
        dim3 g2(DD/32, HID/32, 6);
        wsplit_kernel<<<g2, 256>>>(ff_w2, w2h, w2l, HID, DD, HID, 0, (long long)HID*DD, (long long)HID*DD);
        dim3 g56(DD/32, DD/32, 1);
        wsplit_kernel<<<g56, 256>>>(aOw + (size_t)5*DD*DD, w56h, w56l, DD, DD, 512, 0, 0, 0);
        wsplit_kernel<<<g56, 256>>>(aOw + (size_t)6*DD*DD, w56h, w56l, DD, DD, 512, 256, 0, 0);
        b56_kernel<<<1, DD>>>(aOb);
    }

    float* QKVG[4] = { Qb, Kb, Vb, Gg };

    auto run_ln = [&](int nz, const float* xs[], const float* gbase, const float* bbase,
                      const int* ks, float* outs[]) {
        LnBatch lb;
        for (int j = 0; j < nz; j++)
            lb.s[j] = { xs[j], gbase + (size_t)ks[j]*DD, bbase + (size_t)ks[j]*DD, outs[j] };
        ln_kernel<<<dim3(MM, nz), 256>>>(lb);
    };

    auto run_qkvg = [&](int nz, const int* mods, const float* qsrc[], const float* kvsrc[]) {
        Batch bt = {};
        for (int j = 0; j < nz; j++) {
            int k = mods[j];
            for (int c = 0; c < 4; c++) {
                Slice& s = bt.s[j*4 + c];
                s.A  = (c == 0) ? qsrc[j] : kvsrc[j];
                s.A2 = nullptr;
                const bf16* bh[4] = { wqh, wkh, wvh, gwh };
                const bf16* bl[4] = { wql, wkl, wvl, gwl };
                s.Bh = bh[c] + (size_t)k*DD*DD;
                s.Bl = bl[c] + (size_t)k*DD*DD;
                s.bias = (c == 3) ? (aGb + (size_t)k*DD) : nullptr;
                s.res = nullptr;
                s.C = QKVG[c] + (size_t)j*BSD;
                s.mode = (c == 3) ? 2 : 0;
            }
        }
        gemm_batched<<<dim3(DD/128, MM/128, nz*4), 256, SMEMB>>>(bt, MM, DD, DD);
    };

    auto run_attn = [&](int nz) {
        AtBatch ab = {};
        for (int j = 0; j < nz; j++)
            ab.s[j] = { Qb + (size_t)j*BSD, Kb + (size_t)j*BSD, Vb + (size_t)j*BSD,
                        Gg + (size_t)j*BSD, ctx + (size_t)j*BSD };
        attn_core_kernel<<<dim3((BB*HH*SS*32)/256, nz), 256>>>(ab, mask);
    };

    auto run_proj = [&](int nz, const int* mods, float* const* dst) {
        Batch bt = {};
        for (int j = 0; j < nz; j++) {
            int k = mods[j];
            bt.s[j] = { ctx + (size_t)j*BSD, nullptr,
                        owh + (size_t)k*DD*DD, owl + (size_t)k*DD*DD,
                        aOb + (size_t)k*DD, dst[j], dst[j], 0 };
        }
        gemm_batched<<<dim3(DD/128, MM/128, nz), 256, SMEMB>>>(bt, MM, DD, DD);
    };

    auto run_ff = [&](int nz, const int* mods, float* const* dst) {
        // LN
        LnBatch lb;
        float* tmp[3] = { tA, tB, tC };
        for (int j = 0; j < nz; j++)
            lb.s[j] = { dst[j], ff_g + (size_t)mods[j]*DD, ff_b + (size_t)mods[j]*DD, tmp[j] };
        ln_kernel<<<dim3(MM, nz), 256>>>(lb);
        // FF1 (relu)
        Batch b1 = {};
        for (int j = 0; j < nz; j++)
            b1.s[j] = { tmp[j], nullptr,
                        w1h + (size_t)mods[j]*DD*HID, w1l + (size_t)mods[j]*DD*HID,
                        ff_b1 + (size_t)mods[j]*HID, nullptr, hid + (size_t)j*MH, 1 };
        gemm_batched<<<dim3(HID/128, MM/128, nz), 256, SMEMB>>>(b1, MM, HID, DD);
        // FF2 (+res)
        Batch b2 = {};
        for (int j = 0; j < nz; j++)
            b2.s[j] = { hid + (size_t)j*MH, nullptr,
                        w2h + (size_t)mods[j]*HID*DD, w2l + (size_t)mods[j]*HID*DD,
                        ff_b2 + (size_t)mods[j]*DD, dst[j], dst[j], 0 };
        gemm_batched<<<dim3(DD/128, MM/128, nz), 256, SMEMB>>>(b2, MM, DD, HID);
    };

    for (int it = 0; it < NITER; it++) {
        // -------- Phase 1: self blocks (L, N, O independent) --------
        {
            const float* xs[3] = { L, Nb, O };
            const int lnk[3] = { 0, 1, 2 };
            float* outs[3] = { tA, tB, tC };
            run_ln(3, xs, ln_g, ln_b, lnk, outs);
            const int mods[3] = { 0, 1, 2 };
            const float* qs[3] = { tA, tB, tC };
            run_qkvg(3, mods, qs, qs);
            run_attn(3);
            run_proj(3, mods, X);
            run_ff(3, mods, X);
        }
        // -------- Phase 2: cross blocks (L, N vs tO) --------
        {
            const float* xs[3] = { O, L, Nb };
            const int lnk[3] = { 3, 4, 5 };
            float* outs[3] = { tD, tA, tB };
            run_ln(3, xs, ln_g, ln_b, lnk, outs);
            const int mods[2] = { 3, 4 };
            const float* qs[2] = { tA, tB };
            const float* kv[2] = { tD, tD };
            run_qkvg(2, mods, qs, kv);
            run_attn(2);
            float* dst[2] = { L, Nb };
            run_proj(2, mods, dst);
            run_ff(2, mods, dst);
        }
        // -------- Phase 3: O update from tN and tL --------
        {
            const float* xs[3] = { L, Nb, O };
            const int lnk[3] = { 6, 7, 8 };
            float* outs[3] = { tA, tB, tC };
            run_ln(3, xs, ln_g, ln_b, lnk, outs);
            const int mods[2] = { 5, 6 };
            const float* qs[2] = { tC, tC };
            const float* kv[2] = { tB, tA };
            run_qkvg(2, mods, qs, kv);
            run_attn(2);
            // merged projection: O += [ctx5|ctx6] @ [Ow5;Ow6] + (b5+b6)
            Batch bp = {};
            bp.s[0] = { ctx, ctx + BSD, w56h, w56l, b56, O, O, 0 };
            gemm_batched<<<dim3(DD/128, MM/128, 1), 256, SMEMB>>>(bp, MM, DD, 512);
            const int ffm[1] = { 5 };
            float* dst[1] = { O };
            run_ff(1, ffm, dst);
        }
    }
}

// round 6
// speedup vs baseline: 2.9284x; 1.0345x over previous
#include <cuda_runtime.h>
#include <cuda_bf16.h>
#include <stdint.h>
#include <math.h>

#define BB 2
#define SS 1024
#define DD 256
#define HH 4
#define CC 64
#define WINSZ 10
#define NITER 2
#define MM 2048
#define HID 2048
#define BSD (BB*SS*DD)
#define MH ((size_t)MM*HID)

typedef __nv_bfloat16 bf16;

// ---------------- scratch (device globals; no allocation) -------------------
__device__ float g_Q[3*BSD], g_Kb[3*BSD], g_Vb[3*BSD], g_Gb[3*BSD];
__device__ float g_b56[DD];
// split activations (hi/lo bf16)
__device__ bf16 g_lnh[4*BSD], g_lnl[4*BSD];          // LN outputs, 4 slots
__device__ bf16 g_cth[3*BSD], g_ctl[3*BSD];          // attention ctx
__device__ bf16 g_hidh[3*MH], g_hidl[3*MH];          // FF hidden

// pre-split transposed weights: [N][K] bf16 hi / lo
__device__ bf16 g_WqTh[7*DD*DD], g_WqTl[7*DD*DD];
__device__ bf16 g_WkTh[7*DD*DD], g_WkTl[7*DD*DD];
__device__ bf16 g_WvTh[7*DD*DD], g_WvTl[7*DD*DD];
__device__ bf16 g_GwTh[7*DD*DD], g_GwTl[7*DD*DD];
__device__ bf16 g_OwTh[7*DD*DD], g_OwTl[7*DD*DD];
__device__ bf16 g_w1Th[(size_t)6*DD*HID], g_w1Tl[(size_t)6*DD*HID];
__device__ bf16 g_w2Th[(size_t)6*HID*DD], g_w2Tl[(size_t)6*HID*DD];
__device__ bf16 g_W56h[DD*512], g_W56l[DD*512];

__device__ __forceinline__ void split2(float v, bf16& h, bf16& l){
    h = __float2bfloat16(v);
    l = __float2bfloat16(v - __bfloat162float(h));
}
__device__ __forceinline__ uint32_t smem_u32(const void* p){
    uint32_t a;
    asm("{ .reg .u64 t; cvta.to.shared.u64 t, %1; cvt.u32.u64 %0, t; }" : "=r"(a) : "l"(p));
    return a;
}
__device__ __forceinline__ void cp16(uint32_t saddr, const void* g){
    asm volatile("cp.async.cg.shared.global [%0], [%1], 16;" :: "r"(saddr), "l"(g));
}

// ---------------- weight transpose + split: W[K,N] -> Th/Tl[N][ldt] ---------
__global__ void __launch_bounds__(256) wsplit_kernel(
    const float* __restrict__ W, bf16* __restrict__ Th, bf16* __restrict__ Tl,
    int K, int N, int ldt, int ooff, long long wstride, long long tstride)
{
    const float* w = W + (size_t)blockIdx.z * wstride;
    bf16* th = Th + (size_t)blockIdx.z * tstride;
    bf16* tl = Tl + (size_t)blockIdx.z * tstride;
    __shared__ float sm[32][33];
    int n0 = blockIdx.x * 32, k0 = blockIdx.y * 32;
    int tx = threadIdx.x & 31, ty = threadIdx.x >> 5;
    #pragma unroll
    for (int i = 0; i < 4; i++)
        sm[ty + i*8][tx] = w[(size_t)(k0 + ty + i*8) * N + n0 + tx];
    __syncthreads();
    #pragma unroll
    for (int i = 0; i < 4; i++) {
        int n = n0 + ty + i*8;
        bf16 h, l; split2(sm[tx][ty + i*8], h, l);
        th[(size_t)n * ldt + ooff + k0 + tx] = h;
        tl[(size_t)n * ldt + ooff + k0 + tx] = l;
    }
}

__global__ void b56_kernel(const float* __restrict__ aOb){
    int t = threadIdx.x;
    g_b56[t] = aOb[5*DD + t] + aOb[6*DD + t];
}

// ---------------- LayerNorm (batched over z), split bf16 output -------------
struct LnS { const float* x; const float* g; const float* b; bf16* oh; bf16* ol; };
struct LnBatch { LnS s[3]; };

__global__ void __launch_bounds__(256) ln_kernel(LnBatch lb)
{
    LnS sl = lb.s[blockIdx.y];
    int row = blockIdx.x;
    int t   = threadIdx.x;
    float v = sl.x[(size_t)row * DD + t];
    __shared__ float red[8];
    __shared__ float mean_s, rstd_s;
    float s = v;
    #pragma unroll
    for (int o = 16; o > 0; o >>= 1) s += __shfl_xor_sync(0xffffffffu, s, o);
    if ((t & 31) == 0) red[t >> 5] = s;
    __syncthreads();
    if (t == 0) { float tot=0.f; for (int i=0;i<8;i++) tot+=red[i]; mean_s = tot*(1.0f/DD); }
    __syncthreads();
    float d = v - mean_s;
    s = d * d;
    #pragma unroll
    for (int o = 16; o > 0; o >>= 1) s += __shfl_xor_sync(0xffffffffu, s, o);
    if ((t & 31) == 0) red[t >> 5] = s;
    __syncthreads();
    if (t == 0) { float tot=0.f; for (int i=0;i<8;i++) tot+=red[i]; rstd_s = rsqrtf(tot*(1.0f/DD)+1e-5f); }
    __syncthreads();
    float out = d * rstd_s * sl.g[t] + sl.b[t];
    bf16 h, l; split2(out, h, l);
    sl.oh[(size_t)row * DD + t] = h;
    sl.ol[(size_t)row * DD + t] = l;
}

// ---------------- batched split-compensated MMA GEMM ------------------------
// C[M,N] = epi(concat_k(A,A2)[M,K] @ Wsplit[K,N] + bias) (+res)
// A given pre-split (Ah/Al, optional A2h/A2l for K-concat). Output either
// fp32 C (with optional res) or split pair (Ch/Cl).
struct Slice {
    const bf16 *Ah, *Al, *A2h, *A2l;
    const bf16 *Bh, *Bl;
    const float *bias, *res;
    float* C; bf16 *Ch, *Cl;
    int mode;  // 0 none, 1 relu, 2 sigmoid
};
struct Batch { Slice s[12]; };

#define BKC 32
#define LDSB 40
#define ARRE (128*LDSB)          /* bf16 elems per array */
#define STGE (4*ARRE)            /* per stage: Ah,Al,Bh,Bl */
#define GSMEM (2*STGE*2)         /* bytes: 2 stages */

__device__ __forceinline__ void mma16816(float* c, const uint32_t* a, const uint32_t* b){
    asm volatile("mma.sync.aligned.m16n8k16.row.col.f32.bf16.bf16.f32 "
        "{%0,%1,%2,%3}, {%4,%5,%6,%7}, {%8,%9}, {%0,%1,%2,%3};"
        : "+f"(c[0]), "+f"(c[1]), "+f"(c[2]), "+f"(c[3])
        : "r"(a[0]), "r"(a[1]), "r"(a[2]), "r"(a[3]), "r"(b[0]), "r"(b[1]));
}

__global__ void __launch_bounds__(256,2)
gemm_batched(Batch bt, int M, int N, int K)
{
    extern __shared__ __align__(16) bf16 smem[];
    const Slice sl = bt.s[blockIdx.z];
    const int tid  = threadIdx.x;
    const int warp = tid >> 5, lane = tid & 31;
    const int wm = warp >> 2, wn = warp & 3;
    const int row0 = blockIdx.y * 128, col0 = blockIdx.x * 128;
    const int g8 = lane >> 2, tig = lane & 3;
    const int lda = sl.A2h ? 256 : K;
    const uint32_t sb = smem_u32(smem);
    const int NC = K / BKC;

    float acc[4][4][4];
    #pragma unroll
    for (int i=0;i<4;i++) for (int j=0;j<4;j++) for (int q=0;q<4;q++) acc[i][j][q]=0.f;

    // per-thread 2 chunks of 16B per array
    const int ck0 = tid, ck1 = tid + 256;
    const int r0c = ck0 >> 2, c0c = (ck0 & 3) * 8;
    const int r1c = ck1 >> 2, c1c = (ck1 & 3) * 8;

    auto cpStage = [&](int c, int st){
        int kc = c * BKC;
        const bf16 *pAh = sl.Ah, *pAl = sl.Al; int kl = kc;
        if (sl.A2h && kc >= 256) { pAh = sl.A2h; pAl = sl.A2l; kl = kc - 256; }
        uint32_t base = sb + (uint32_t)(st * STGE) * 2;
        uint32_t so0 = (uint32_t)(r0c * LDSB + c0c) * 2;
        uint32_t so1 = (uint32_t)(r1c * LDSB + c1c) * 2;
        cp16(base + so0,              pAh + (size_t)(row0 + r0c) * lda + kl + c0c);
        cp16(base + so1,              pAh + (size_t)(row0 + r1c) * lda + kl + c1c);
        cp16(base + ARRE*2   + so0,   pAl + (size_t)(row0 + r0c) * lda + kl + c0c);
        cp16(base + ARRE*2   + so1,   pAl + (size_t)(row0 + r1c) * lda + kl + c1c);
        cp16(base + ARRE*4   + so0,   sl.Bh + (size_t)(col0 + r0c) * K + kc + c0c);
        cp16(base + ARRE*4   + so1,   sl.Bh + (size_t)(col0 + r1c) * K + kc + c1c);
        cp16(base + ARRE*6   + so0,   sl.Bl + (size_t)(col0 + r0c) * K + kc + c0c);
        cp16(base + ARRE*6   + so1,   sl.Bl + (size_t)(col0 + r1c) * K + kc + c1c);
        asm volatile("cp.async.commit_group;" ::: "memory");
    };

    cpStage(0, 0);
    if (NC > 1) cpStage(1, 1);
    else asm volatile("cp.async.commit_group;" ::: "memory");

    for (int c = 0; c < NC; c++) {
        const int st = c & 1;
        if (c + 2 < NC) asm volatile("cp.async.wait_group 1;" ::: "memory");
        else            asm volatile("cp.async.wait_group 0;" ::: "memory");
        __syncthreads();

        const bf16* Ash = smem + st*STGE;
        const bf16* Asl = Ash + ARRE;
        const bf16* Bsh = Ash + 2*ARRE;
        const bf16* Bsl = Ash + 3*ARRE;

        #pragma unroll
        for (int kk = 0; kk < 2; kk++) {
            int kb = kk*16 + tig*2;
            uint32_t bh[4][2], bl[4][2];
            #pragma unroll
            for (int ni = 0; ni < 4; ni++) {
                int n = wn*32 + ni*8 + g8;
                const bf16* pbh = &Bsh[n*LDSB + kb];
                const bf16* pbl = &Bsl[n*LDSB + kb];
                bh[ni][0] = *(const uint32_t*)pbh;
                bh[ni][1] = *(const uint32_t*)(pbh+8);
                bl[ni][0] = *(const uint32_t*)pbl;
                bl[ni][1] = *(const uint32_t*)(pbl+8);
            }
            #pragma unroll
            for (int mi = 0; mi < 4; mi++) {
                int r = wm*64 + mi*16 + g8;
                const bf16* pah = &Ash[r*LDSB + kb];
                const bf16* pal = &Asl[r*LDSB + kb];
                uint32_t ah[4], al[4];
                ah[0] = *(const uint32_t*)pah;
                ah[1] = *(const uint32_t*)(pah + 8*LDSB);
                ah[2] = *(const uint32_t*)(pah + 8);
                ah[3] = *(const uint32_t*)(pah + 8*LDSB + 8);
                al[0] = *(const uint32_t*)pal;
                al[1] = *(const uint32_t*)(pal + 8*LDSB);
                al[2] = *(const uint32_t*)(pal + 8);
                al[3] = *(const uint32_t*)(pal + 8*LDSB + 8);
                #pragma unroll
                for (int ni = 0; ni < 4; ni++) {
                    mma16816(acc[mi][ni], ah, bh[ni]);
                    mma16816(acc[mi][ni], ah, bl[ni]);
                    mma16816(acc[mi][ni], al, bh[ni]);
                }
            }
        }
        __syncthreads();
        if (c + 2 < NC) cpStage(c + 2, st);
    }

    // epilogue
    #pragma unroll
    for (int mi = 0; mi < 4; mi++) {
        #pragma unroll
        for (int ni = 0; ni < 4; ni++) {
            int r1 = row0 + wm*64 + mi*16 + g8;
            int c1 = col0 + wn*32 + ni*8 + tig*2;
            #pragma unroll
            for (int q = 0; q < 4; q++) {
                int r = (q < 2) ? r1 : r1 + 8;
                int cc = c1 + (q & 1);
                float v = acc[mi][ni][q];
                if (sl.bias) v += sl.bias[cc];
                if (sl.mode == 1)      v = fmaxf(v, 0.f);
                else if (sl.mode == 2) v = 1.f / (1.f + __expf(-v));
                if (sl.Ch) {
                    bf16 h, l; split2(v, h, l);
                    sl.Ch[(size_t)r * N + cc] = h;
                    sl.Cl[(size_t)r * N + cc] = l;
                } else {
                    if (sl.res) v += sl.res[(size_t)r * N + cc];
                    sl.C[(size_t)r * N + cc] = v;
                }
            }
        }
    }
}

// ---------------- windowed attention core (batched over z) ------------------
struct AtS { const float* Q; const float* K; const float* V; const float* G;
             bf16* cth; bf16* ctl; };
struct AtBatch { AtS s[3]; };

__global__ void __launch_bounds__(256)
attn_core_kernel(AtBatch ab, const unsigned char* __restrict__ mask)
{
    AtS sl = ab.s[blockIdx.y];
    int idx  = blockIdx.x * blockDim.x + threadIdx.x;
    int gw   = idx >> 5;
    int lane = idx & 31;
    int s = gw & (SS - 1);
    int h = (gw >> 10) & (HH - 1);
    int n = gw >> 12;

    int base_q = (n * SS + s) * DD + h * CC;
    float q0 = sl.Q[base_q + lane];
    float q1 = sl.Q[base_q + 32 + lane];

    int t0 = s - WINSZ; if (t0 < 0) t0 = 0;
    int t1 = s + WINSZ; if (t1 > SS - 1) t1 = SS - 1;
    int cnt = t1 - t0 + 1;

    float sc[2 * WINSZ + 1];
    float mx = -1e30f;
    for (int i = 0; i < cnt; i++) {
        int t = t0 + i;
        float v;
        if (mask[n * SS + t]) v = -1e30f;
        else {
            int bk = (n * SS + t) * DD + h * CC;
            float p = q0 * sl.K[bk + lane] + q1 * sl.K[bk + 32 + lane];
            #pragma unroll
            for (int o = 16; o > 0; o >>= 1) p += __shfl_xor_sync(0xffffffffu, p, o);
            v = p * 0.125f;
        }
        sc[i] = v;
        mx = fmaxf(mx, v);
    }
    float denom = 0.f;
    for (int i = 0; i < cnt; i++) {
        float e = (sc[i] <= -1e29f) ? 0.f : __expf(sc[i] - mx);
        sc[i] = e; denom += e;
    }
    float inv = (denom > 0.f) ? (1.f / denom) : 0.f;
    float o0 = 0.f, o1 = 0.f;
    for (int i = 0; i < cnt; i++) {
        int bv = (n * SS + (t0 + i)) * DD + h * CC;
        float a = sc[i] * inv;
        o0 = fmaf(a, sl.V[bv + lane], o0);
        o1 = fmaf(a, sl.V[bv + 32 + lane], o1);
    }
    float v0 = o0 * sl.G[base_q + lane];
    float v1 = o1 * sl.G[base_q + 32 + lane];
    bf16 h0, l0, h1, l1;
    split2(v0, h0, l0); split2(v1, h1, l1);
    sl.cth[base_q + lane]      = h0;  sl.ctl[base_q + lane]      = l0;
    sl.cth[base_q + 32 + lane] = h1;  sl.ctl[base_q + 32 + lane] = l1;
}

// ---------------- host orchestration ----------------------------------------
extern "C" void kernel_launch(void* const* d_in, const int* in_sizes, int n_in,
                              void* d_out, int out_size)
{
    (void)in_sizes; (void)n_in; (void)out_size;
    const float* inL = (const float*)d_in[0];
    const float* inN = (const float*)d_in[1];
    const float* inO = (const float*)d_in[2];
    const unsigned char* mask = (const unsigned char*)d_in[3];
    const float* aWq = (const float*)d_in[4];
    const float* aWk = (const float*)d_in[5];
    const float* aWv = (const float*)d_in[6];
    const float* aGw = (const float*)d_in[7];
    const float* aGb = (const float*)d_in[8];
    const float* aOw = (const float*)d_in[9];
    const float* aOb = (const float*)d_in[10];
    const float* ln_g = (const float*)d_in[11];
    const float* ln_b = (const float*)d_in[12];
    const float* ff_g = (const float*)d_in[13];
    const float* ff_b = (const float*)d_in[14];
    const float* ff_w1 = (const float*)d_in[15];
    const float* ff_b1 = (const float*)d_in[16];
    const float* ff_w2 = (const float*)d_in[17];
    const float* ff_b2 = (const float*)d_in[18];

    float* L  = (float*)d_out;
    float* Nb = L + BSD;
    float* O  = Nb + BSD;
    float* X[3] = { L, Nb, O };

    cudaMemcpyAsync(L,  inL, (size_t)BSD * sizeof(float), cudaMemcpyDeviceToDevice);
    cudaMemcpyAsync(Nb, inN, (size_t)BSD * sizeof(float), cudaMemcpyDeviceToDevice);
    cudaMemcpyAsync(O,  inO, (size_t)BSD * sizeof(float), cudaMemcpyDeviceToDevice);

    void* pa;
    #define SYM(var, sym) cudaGetSymbolAddress(&pa, sym); auto var = (decltype(&sym[0]))pa;
    SYM(Qb, g_Q) SYM(Kb, g_Kb) SYM(Vb, g_Vb) SYM(Gg, g_Gb)
    SYM(lnh, g_lnh) SYM(lnl, g_lnl)
    SYM(cth, g_cth) SYM(ctl, g_ctl)
    SYM(hidh, g_hidh) SYM(hidl, g_hidl)
    SYM(b56, g_b56)
    SYM(wqh, g_WqTh) SYM(wql, g_WqTl) SYM(wkh, g_WkTh) SYM(wkl, g_WkTl)
    SYM(wvh, g_WvTh) SYM(wvl, g_WvTl) SYM(gwh, g_GwTh) SYM(gwl, g_GwTl)
    SYM(owh, g_OwTh) SYM(owl, g_OwTl)
    SYM(w1h, g_w1Th) SYM(w1l, g_w1Tl) SYM(w2h, g_w2Th) SYM(w2l, g_w2Tl)
    SYM(w56h, g_W56h) SYM(w56l, g_W56l)
    #undef SYM

    cudaFuncSetAttribute(gemm_batched, cudaFuncAttributeMaxDynamicSharedMemorySize, GSMEM);

    // ---- weight prep ----
    {
        dim3 gA(DD/32, DD/32, 7);
        wsplit_kernel<<<gA, 256>>>(aWq, wqh, wql, DD, DD, DD, 0, DD*DD, DD*DD);
        wsplit_kernel<<<gA, 256>>>(aWk, wkh, wkl, DD, DD, DD, 0, DD*DD, DD*DD);
        wsplit_kernel<<<gA, 256>>>(aWv, wvh, wvl, DD, DD, DD, 0, DD*DD, DD*DD);
        wsplit_kernel<<<gA, 256>>>(aGw, gwh, gwl, DD, DD, DD, 0, DD*DD, DD*DD);
        wsplit_kernel<<<gA, 256>>>(aOw, owh, owl, DD, DD, DD, 0, DD*DD, DD*DD);
        dim3 g1(HID/32, DD/32, 6);
        wsplit_kernel<<<g1, 256>>>(ff_w1, w1h, w1l, DD, HID, DD, 0, (long long)DD*HID, (long long)DD*HID);
        dim3 g2(DD/32, HID/32, 6);
        wsplit_kernel<<<g2, 256>>>(ff_w2, w2h, w2l, HID, DD, HID, 0, (long long)HID*DD, (long long)HID*DD);
        dim3 g56(DD/32, DD/32, 1);
        wsplit_kernel<<<g56, 256>>>(aOw + (size_t)5*DD*DD, w56h, w56l, DD, DD, 512, 0, 0, 0);
        wsplit_kernel<<<g56, 256>>>(aOw + (size_t)6*DD*DD, w56h, w56l, DD, DD, 512, 256, 0, 0);
        b56_kernel<<<1, DD>>>(aOb);
    }

    float* QKVG[4] = { Qb, Kb, Vb, Gg };

    auto run_ln = [&](int nz, const float* xs[], const float* gbase, const float* bbase,
                      const int* ks, const int* slots) {
        LnBatch lb;
        for (int j = 0; j < nz; j++)
            lb.s[j] = { xs[j], gbase + (size_t)ks[j]*DD, bbase + (size_t)ks[j]*DD,
                        lnh + (size_t)slots[j]*BSD, lnl + (size_t)slots[j]*BSD };
        ln_kernel<<<dim3(MM, nz), 256>>>(lb);
    };

    auto run_qkvg = [&](int nz, const int* mods, const int* qslot, const int* kvslot) {
        Batch bt = {};
        for (int j = 0; j < nz; j++) {
            int k = mods[j];
            for (int c = 0; c < 4; c++) {
                Slice& s = bt.s[j*4 + c];
                int slot = (c == 0) ? qslot[j] : kvslot[j];
                s.Ah = lnh + (size_t)slot*BSD;
                s.Al = lnl + (size_t)slot*BSD;
                const bf16* bh[4] = { wqh, wkh, wvh, gwh };
                const bf16* bl[4] = { wql, wkl, wvl, gwl };
                s.Bh = bh[c] + (size_t)k*DD*DD;
                s.Bl = bl[c] + (size_t)k*DD*DD;
                s.bias = (c == 3) ? (aGb + (size_t)k*DD) : nullptr;
                s.C = QKVG[c] + (size_t)j*BSD;
                s.mode = (c == 3) ? 2 : 0;
            }
        }
        gemm_batched<<<dim3(DD/128, MM/128, nz*4), 256, GSMEM>>>(bt, MM, DD, DD);
    };

    auto run_attn = [&](int nz) {
        AtBatch ab = {};
        for (int j = 0; j < nz; j++)
            ab.s[j] = { Qb + (size_t)j*BSD, Kb + (size_t)j*BSD, Vb + (size_t)j*BSD,
                        Gg + (size_t)j*BSD, cth + (size_t)j*BSD, ctl + (size_t)j*BSD };
        attn_core_kernel<<<dim3((BB*HH*SS*32)/256, nz), 256>>>(ab, mask);
    };

    auto run_proj = [&](int nz, const int* mods, float* const* dst) {
        Batch bt = {};
        for (int j = 0; j < nz; j++) {
            int k = mods[j];
            Slice& s = bt.s[j];
            s.Ah = cth + (size_t)j*BSD;
            s.Al = ctl + (size_t)j*BSD;
            s.Bh = owh + (size_t)k*DD*DD;
            s.Bl = owl + (size_t)k*DD*DD;
            s.bias = aOb + (size_t)k*DD;
            s.res = dst[j]; s.C = dst[j];
        }
        gemm_batched<<<dim3(DD/128, MM/128, nz), 256, GSMEM>>>(bt, MM, DD, DD);
    };

    auto run_ff = [&](int nz, const int* mods, float* const* dst) {
        // LN -> slots 0..nz-1
        LnBatch lb;
        for (int j = 0; j < nz; j++)
            lb.s[j] = { dst[j], ff_g + (size_t)mods[j]*DD, ff_b + (size_t)mods[j]*DD,
                        lnh + (size_t)j*BSD, lnl + (size_t)j*BSD };
        ln_kernel<<<dim3(MM, nz), 256>>>(lb);
        // FF1 (relu, split output)
        Batch b1 = {};
        for (int j = 0; j < nz; j++) {
            Slice& s = b1.s[j];
            s.Ah = lnh + (size_t)j*BSD; s.Al = lnl + (size_t)j*BSD;
            s.Bh = w1h + (size_t)mods[j]*DD*HID; s.Bl = w1l + (size_t)mods[j]*DD*HID;
            s.bias = ff_b1 + (size_t)mods[j]*HID;
            s.Ch = hidh + (size_t)j*MH; s.Cl = hidl + (size_t)j*MH;
            s.mode = 1;
        }
        gemm_batched<<<dim3(HID/128, MM/128, nz), 256, GSMEM>>>(b1, MM, HID, DD);
        // FF2 (+res)
        Batch b2 = {};
        for (int j = 0; j < nz; j++) {
            Slice& s = b2.s[j];
            s.Ah = hidh + (size_t)j*MH; s.Al = hidl + (size_t)j*MH;
            s.Bh = w2h + (size_t)mods[j]*HID*DD; s.Bl = w2l + (size_t)mods[j]*HID*DD;
            s.bias = ff_b2 + (size_t)mods[j]*DD;
            s.res = dst[j]; s.C = dst[j];
        }
        gemm_batched<<<dim3(DD/128, MM/128, nz), 256, GSMEM>>>(b2, MM, DD, HID);
    };

    for (int it = 0; it < NITER; it++) {
        // -------- Phase 1: self blocks (L, N, O independent) --------
        {
            const float* xs[3] = { L, Nb, O };
            const int lnk[3] = { 0, 1, 2 };
            const int slots[3] = { 0, 1, 2 };
            run_ln(3, xs, ln_g, ln_b, lnk, slots);
            const int mods[3] = { 0, 1, 2 };
            run_qkvg(3, mods, slots, slots);
            run_attn(3);
            run_proj(3, mods, X);
            run_ff(3, mods, X);
        }
        // -------- Phase 2: cross blocks (L, N vs tO) --------
        {
            const float* xs[3] = { O, L, Nb };
            const int lnk[3] = { 3, 4, 5 };
            const int slots[3] = { 3, 0, 1 };      // tO in slot 3, tL slot 0, tN slot 1
            run_ln(3, xs, ln_g, ln_b, lnk, slots);
            const int mods[2] = { 3, 4 };
            const int qslot[2] = { 0, 1 };
            const int kvslot[2] = { 3, 3 };
            run_qkvg(2, mods, qslot, kvslot);
            run_attn(2);
            float* dst[2] = { L, Nb };
            run_proj(2, mods, dst);
            run_ff(2, mods, dst);
        }
        // -------- Phase 3: O update from tN and tL --------
        {
            const float* xs[3] = { L, Nb, O };
            const int lnk[3] = { 6, 7, 8 };
            const int slots[3] = { 0, 1, 2 };      // tL, tN, tO
            run_ln(3, xs, ln_g, ln_b, lnk, slots);
            const int mods[2] = { 5, 6 };
            const int qslot[2] = { 2, 2 };
            const int kvslot[2] = { 1, 0 };
            run_qkvg(2, mods, qslot, kvslot);
            run_attn(2);
            // merged projection: O += [ctx5|ctx6] @ [Ow5;Ow6] + (b5+b6)
            Batch bp = {};
            bp.s[0].Ah = cth; bp.s[0].Al = ctl;
            bp.s[0].A2h = cth + BSD; bp.s[0].A2l = ctl + BSD;
            bp.s[0].Bh = w56h; bp.s[0].Bl = w56l;
            bp.s[0].bias = b56; bp.s[0].res = O; bp.s[0].C = O;
            gemm_batched<<<dim3(DD/128, MM/128, 1), 256, GSMEM>>>(bp, MM, DD, 512);
            const int ffm[1] = { 5 };
            float* dst[1] = { O };
            run_ff(1, ffm, dst);
        }
    }
}

// round 7
// speedup vs baseline: 2.9584x; 1.0103x over previous
#include <cuda_runtime.h>
#include <cuda_bf16.h>
#include <stdint.h>
#include <math.h>

#define BB 2
#define SS 1024
#define DD 256
#define HH 4
#define CC 64
#define WINSZ 10
#define NITER 2
#define MM 2048
#define HID 2048
#define BSD (BB*SS*DD)
#define MH ((size_t)MM*HID)

typedef __nv_bfloat16 bf16;

// ---------------- scratch (device globals; no allocation) -------------------
__device__ float g_Q[3*BSD], g_Kb[3*BSD], g_Vb[3*BSD], g_Gb[3*BSD];
__device__ float g_b56[DD];
__device__ bf16 g_lnh[4*BSD], g_lnl[4*BSD];
__device__ bf16 g_cth[3*BSD], g_ctl[3*BSD];
__device__ bf16 g_hidh[3*MH], g_hidl[3*MH];

__device__ bf16 g_WqTh[7*DD*DD], g_WqTl[7*DD*DD];
__device__ bf16 g_WkTh[7*DD*DD], g_WkTl[7*DD*DD];
__device__ bf16 g_WvTh[7*DD*DD], g_WvTl[7*DD*DD];
__device__ bf16 g_GwTh[7*DD*DD], g_GwTl[7*DD*DD];
__device__ bf16 g_OwTh[7*DD*DD], g_OwTl[7*DD*DD];
__device__ bf16 g_w1Th[(size_t)6*DD*HID], g_w1Tl[(size_t)6*DD*HID];
__device__ bf16 g_w2Th[(size_t)6*HID*DD], g_w2Tl[(size_t)6*HID*DD];
__device__ bf16 g_W56h[DD*512], g_W56l[DD*512];

__device__ __forceinline__ void split2(float v, bf16& h, bf16& l){
    h = __float2bfloat16(v);
    l = __float2bfloat16(v - __bfloat162float(h));
}
__device__ __forceinline__ uint32_t smem_u32(const void* p){
    uint32_t a;
    asm("{ .reg .u64 t; cvta.to.shared.u64 t, %1; cvt.u32.u64 %0, t; }" : "=r"(a) : "l"(p));
    return a;
}
__device__ __forceinline__ void cp16(uint32_t saddr, const void* g){
    asm volatile("cp.async.cg.shared.global [%0], [%1], 16;" :: "r"(saddr), "l"(g));
}
__device__ __forceinline__ void ldsm_x4(uint32_t* r, uint32_t addr){
    asm volatile("ldmatrix.sync.aligned.m8n8.x4.shared.b16 {%0,%1,%2,%3}, [%4];"
        : "=r"(r[0]), "=r"(r[1]), "=r"(r[2]), "=r"(r[3]) : "r"(addr));
}

// ---------------- weight transpose + split: W[K,N] -> Th/Tl[N][ldt] ---------
__global__ void __launch_bounds__(256) wsplit_kernel(
    const float* __restrict__ W, bf16* __restrict__ Th, bf16* __restrict__ Tl,
    int K, int N, int ldt, int ooff, long long wstride, long long tstride)
{
    const float* w = W + (size_t)blockIdx.z * wstride;
    bf16* th = Th + (size_t)blockIdx.z * tstride;
    bf16* tl = Tl + (size_t)blockIdx.z * tstride;
    __shared__ float sm[32][33];
    int n0 = blockIdx.x * 32, k0 = blockIdx.y * 32;
    int tx = threadIdx.x & 31, ty = threadIdx.x >> 5;
    #pragma unroll
    for (int i = 0; i < 4; i++)
        sm[ty + i*8][tx] = w[(size_t)(k0 + ty + i*8) * N + n0 + tx];
    __syncthreads();
    #pragma unroll
    for (int i = 0; i < 4; i++) {
        int n = n0 + ty + i*8;
        bf16 h, l; split2(sm[tx][ty + i*8], h, l);
        th[(size_t)n * ldt + ooff + k0 + tx] = h;
        tl[(size_t)n * ldt + ooff + k0 + tx] = l;
    }
}

__global__ void b56_kernel(const float* __restrict__ aOb){
    int t = threadIdx.x;
    g_b56[t] = aOb[5*DD + t] + aOb[6*DD + t];
}

// ---------------- LayerNorm (batched over z), split bf16 output -------------
struct LnS { const float* x; const float* g; const float* b; bf16* oh; bf16* ol; };
struct LnBatch { LnS s[3]; };

__global__ void __launch_bounds__(256) ln_kernel(LnBatch lb)
{
    LnS sl = lb.s[blockIdx.y];
    int row = blockIdx.x;
    int t   = threadIdx.x;
    float v = sl.x[(size_t)row * DD + t];
    __shared__ float red[8];
    __shared__ float mean_s, rstd_s;
    float s = v;
    #pragma unroll
    for (int o = 16; o > 0; o >>= 1) s += __shfl_xor_sync(0xffffffffu, s, o);
    if ((t & 31) == 0) red[t >> 5] = s;
    __syncthreads();
    if (t == 0) { float tot=0.f; for (int i=0;i<8;i++) tot+=red[i]; mean_s = tot*(1.0f/DD); }
    __syncthreads();
    float d = v - mean_s;
    s = d * d;
    #pragma unroll
    for (int o = 16; o > 0; o >>= 1) s += __shfl_xor_sync(0xffffffffu, s, o);
    if ((t & 31) == 0) red[t >> 5] = s;
    __syncthreads();
    if (t == 0) { float tot=0.f; for (int i=0;i<8;i++) tot+=red[i]; rstd_s = rsqrtf(tot*(1.0f/DD)+1e-5f); }
    __syncthreads();
    float out = d * rstd_s * sl.g[t] + sl.b[t];
    bf16 h, l; split2(out, h, l);
    sl.oh[(size_t)row * DD + t] = h;
    sl.ol[(size_t)row * DD + t] = l;
}

// ---------------- batched split-compensated MMA GEMM ------------------------
struct Slice {
    const bf16 *Ah, *Al, *A2h, *A2l;
    const bf16 *Bh, *Bl;
    const float *bias, *res;
    float* C; bf16 *Ch, *Cl;
    int mode;
};
struct Batch { Slice s[12]; };

#define BKC 32
#define LDSB 40
#define ARRE (128*LDSB)
#define STGE (4*ARRE)
#define GSMEM (2*STGE*2)

__device__ __forceinline__ void mma16816(float* c, const uint32_t* a, const uint32_t* b){
    asm volatile("mma.sync.aligned.m16n8k16.row.col.f32.bf16.bf16.f32 "
        "{%0,%1,%2,%3}, {%4,%5,%6,%7}, {%8,%9}, {%0,%1,%2,%3};"
        : "+f"(c[0]), "+f"(c[1]), "+f"(c[2]), "+f"(c[3])
        : "r"(a[0]), "r"(a[1]), "r"(a[2]), "r"(a[3]), "r"(b[0]), "r"(b[1]));
}

__global__ void __launch_bounds__(256,2)
gemm_batched(Batch bt, int M, int N, int K)
{
    extern __shared__ __align__(16) bf16 smem[];
    const Slice sl = bt.s[blockIdx.z];
    const int tid  = threadIdx.x;
    const int warp = tid >> 5, lane = tid & 31;
    const int wm = warp >> 2, wn = warp & 3;
    const int row0 = blockIdx.y * 128, col0 = blockIdx.x * 128;
    const int g8 = lane >> 2, tig = lane & 3;
    const int lda = sl.A2h ? 256 : K;
    const uint32_t sb = smem_u32(smem);
    const int NC = K / BKC;

    float acc[4][4][4];
    #pragma unroll
    for (int i=0;i<4;i++) for (int j=0;j<4;j++) for (int q=0;q<4;q++) acc[i][j][q]=0.f;

    const int ck0 = tid, ck1 = tid + 256;
    const int r0c = ck0 >> 2, c0c = (ck0 & 3) * 8;
    const int r1c = ck1 >> 2, c1c = (ck1 & 3) * 8;

    // ldmatrix lane-address components
    const int lmat = lane >> 3, lrow = lane & 7;
    // A: row offset (mat&1)*8, col offset (mat>>1)*8
    const uint32_t a_lane_off = (uint32_t)(((lmat & 1) * 8 + lrow) * LDSB + (lmat >> 1) * 8) * 2;
    // B: row offset (mat>>1)*8, col offset (mat&1)*8
    const uint32_t b_lane_off = (uint32_t)(((lmat >> 1) * 8 + lrow) * LDSB + (lmat & 1) * 8) * 2;

    auto cpStage = [&](int c, int st){
        int kc = c * BKC;
        const bf16 *pAh = sl.Ah, *pAl = sl.Al; int kl = kc;
        if (sl.A2h && kc >= 256) { pAh = sl.A2h; pAl = sl.A2l; kl = kc - 256; }
        uint32_t base = sb + (uint32_t)(st * STGE) * 2;
        uint32_t so0 = (uint32_t)(r0c * LDSB + c0c) * 2;
        uint32_t so1 = (uint32_t)(r1c * LDSB + c1c) * 2;
        cp16(base + so0,              pAh + (size_t)(row0 + r0c) * lda + kl + c0c);
        cp16(base + so1,              pAh + (size_t)(row0 + r1c) * lda + kl + c1c);
        cp16(base + ARRE*2   + so0,   pAl + (size_t)(row0 + r0c) * lda + kl + c0c);
        cp16(base + ARRE*2   + so1,   pAl + (size_t)(row0 + r1c) * lda + kl + c1c);
        cp16(base + ARRE*4   + so0,   sl.Bh + (size_t)(col0 + r0c) * K + kc + c0c);
        cp16(base + ARRE*4   + so1,   sl.Bh + (size_t)(col0 + r1c) * K + kc + c1c);
        cp16(base + ARRE*6   + so0,   sl.Bl + (size_t)(col0 + r0c) * K + kc + c0c);
        cp16(base + ARRE*6   + so1,   sl.Bl + (size_t)(col0 + r1c) * K + kc + c1c);
        asm volatile("cp.async.commit_group;" ::: "memory");
    };

    cpStage(0, 0);
    if (NC > 1) cpStage(1, 1);
    else asm volatile("cp.async.commit_group;" ::: "memory");

    for (int c = 0; c < NC; c++) {
        const int st = c & 1;
        if (c + 2 < NC) asm volatile("cp.async.wait_group 1;" ::: "memory");
        else            asm volatile("cp.async.wait_group 0;" ::: "memory");
        __syncthreads();

        const uint32_t sA_h = sb + (uint32_t)(st*STGE) * 2;
        const uint32_t sA_l = sA_h + ARRE*2;
        const uint32_t sB_h = sA_h + ARRE*4;
        const uint32_t sB_l = sA_h + ARRE*6;

        #pragma unroll
        for (int kk = 0; kk < 2; kk++) {
            const uint32_t kbo = (uint32_t)(kk * 16) * 2;
            // B fragments: pairs (ni0,ni1) and (ni2,ni3) via x4
            uint32_t bh[4][2], bl[4][2];
            #pragma unroll
            for (int pr = 0; pr < 2; pr++) {
                uint32_t nbase = (uint32_t)((wn*32 + pr*16) * LDSB) * 2;
                uint32_t r4[4];
                ldsm_x4(r4, sB_h + nbase + kbo + b_lane_off);
                bh[pr*2][0] = r4[0]; bh[pr*2][1] = r4[1];
                bh[pr*2+1][0] = r4[2]; bh[pr*2+1][1] = r4[3];
                ldsm_x4(r4, sB_l + nbase + kbo + b_lane_off);
                bl[pr*2][0] = r4[0]; bl[pr*2][1] = r4[1];
                bl[pr*2+1][0] = r4[2]; bl[pr*2+1][1] = r4[3];
            }
            #pragma unroll
            for (int mi = 0; mi < 4; mi++) {
                uint32_t rbase = (uint32_t)((wm*64 + mi*16) * LDSB) * 2;
                uint32_t ah[4], al[4];
                ldsm_x4(ah, sA_h + rbase + kbo + a_lane_off);
                ldsm_x4(al, sA_l + rbase + kbo + a_lane_off);
                #pragma unroll
                for (int ni = 0; ni < 4; ni++) {
                    mma16816(acc[mi][ni], ah, bh[ni]);
                    mma16816(acc[mi][ni], ah, bl[ni]);
                    mma16816(acc[mi][ni], al, bh[ni]);
                }
            }
        }
        __syncthreads();
        if (c + 2 < NC) cpStage(c + 2, st);
    }

    // epilogue
    #pragma unroll
    for (int mi = 0; mi < 4; mi++) {
        #pragma unroll
        for (int ni = 0; ni < 4; ni++) {
            int r1 = row0 + wm*64 + mi*16 + g8;
            int c1 = col0 + wn*32 + ni*8 + tig*2;
            #pragma unroll
            for (int q = 0; q < 4; q++) {
                int r = (q < 2) ? r1 : r1 + 8;
                int cc = c1 + (q & 1);
                float v = acc[mi][ni][q];
                if (sl.bias) v += sl.bias[cc];
                if (sl.mode == 1)      v = fmaxf(v, 0.f);
                else if (sl.mode == 2) v = 1.f / (1.f + __expf(-v));
                if (sl.Ch) {
                    bf16 h, l; split2(v, h, l);
                    sl.Ch[(size_t)r * N + cc] = h;
                    sl.Cl[(size_t)r * N + cc] = l;
                } else {
                    if (sl.res) v += sl.res[(size_t)r * N + cc];
                    sl.C[(size_t)r * N + cc] = v;
                }
            }
        }
    }
}

// ---------------- windowed attention core (batched over z) ------------------
struct AtS { const float* Q; const float* K; const float* V; const float* G;
             bf16* cth; bf16* ctl; };
struct AtBatch { AtS s[3]; };

__global__ void __launch_bounds__(256)
attn_core_kernel(AtBatch ab, const unsigned char* __restrict__ mask)
{
    AtS sl = ab.s[blockIdx.y];
    int idx  = blockIdx.x * blockDim.x + threadIdx.x;
    int gw   = idx >> 5;
    int lane = idx & 31;
    int s = gw & (SS - 1);
    int h = (gw >> 10) & (HH - 1);
    int n = gw >> 12;

    int base_q = (n * SS + s) * DD + h * CC;
    float q0 = sl.Q[base_q + lane];
    float q1 = sl.Q[base_q + 32 + lane];

    int t0 = s - WINSZ; if (t0 < 0) t0 = 0;
    int t1 = s + WINSZ; if (t1 > SS - 1) t1 = SS - 1;
    int cnt = t1 - t0 + 1;

    float sc[2 * WINSZ + 1];
    float mx = -1e30f;
    for (int i = 0; i < cnt; i++) {
        int t = t0 + i;
        float v;
        if (mask[n * SS + t]) v = -1e30f;
        else {
            int bk = (n * SS + t) * DD + h * CC;
            float p = q0 * sl.K[bk + lane] + q1 * sl.K[bk + 32 + lane];
            #pragma unroll
            for (int o = 16; o > 0; o >>= 1) p += __shfl_xor_sync(0xffffffffu, p, o);
            v = p * 0.125f;
        }
        sc[i] = v;
        mx = fmaxf(mx, v);
    }
    float denom = 0.f;
    for (int i = 0; i < cnt; i++) {
        float e = (sc[i] <= -1e29f) ? 0.f : __expf(sc[i] - mx);
        sc[i] = e; denom += e;
    }
    float inv = (denom > 0.f) ? (1.f / denom) : 0.f;
    float o0 = 0.f, o1 = 0.f;
    for (int i = 0; i < cnt; i++) {
        int bv = (n * SS + (t0 + i)) * DD + h * CC;
        float a = sc[i] * inv;
        o0 = fmaf(a, sl.V[bv + lane], o0);
        o1 = fmaf(a, sl.V[bv + 32 + lane], o1);
    }
    float v0 = o0 * sl.G[base_q + lane];
    float v1 = o1 * sl.G[base_q + 32 + lane];
    bf16 h0, l0, h1, l1;
    split2(v0, h0, l0); split2(v1, h1, l1);
    sl.cth[base_q + lane]      = h0;  sl.ctl[base_q + lane]      = l0;
    sl.cth[base_q + 32 + lane] = h1;  sl.ctl[base_q + 32 + lane] = l1;
}

// ---------------- host orchestration ----------------------------------------
extern "C" void kernel_launch(void* const* d_in, const int* in_sizes, int n_in,
                              void* d_out, int out_size)
{
    (void)in_sizes; (void)n_in; (void)out_size;
    const float* inL = (const float*)d_in[0];
    const float* inN = (const float*)d_in[1];
    const float* inO = (const float*)d_in[2];
    const unsigned char* mask = (const unsigned char*)d_in[3];
    const float* aWq = (const float*)d_in[4];
    const float* aWk = (const float*)d_in[5];
    const float* aWv = (const float*)d_in[6];
    const float* aGw = (const float*)d_in[7];
    const float* aGb = (const float*)d_in[8];
    const float* aOw = (const float*)d_in[9];
    const float* aOb = (const float*)d_in[10];
    const float* ln_g = (const float*)d_in[11];
    const float* ln_b = (const float*)d_in[12];
    const float* ff_g = (const float*)d_in[13];
    const float* ff_b = (const float*)d_in[14];
    const float* ff_w1 = (const float*)d_in[15];
    const float* ff_b1 = (const float*)d_in[16];
    const float* ff_w2 = (const float*)d_in[17];
    const float* ff_b2 = (const float*)d_in[18];

    float* L  = (float*)d_out;
    float* Nb = L + BSD;
    float* O  = Nb + BSD;
    float* X[3] = { L, Nb, O };

    cudaMemcpyAsync(L,  inL, (size_t)BSD * sizeof(float), cudaMemcpyDeviceToDevice);
    cudaMemcpyAsync(Nb, inN, (size_t)BSD * sizeof(float), cudaMemcpyDeviceToDevice);
    cudaMemcpyAsync(O,  inO, (size_t)BSD * sizeof(float), cudaMemcpyDeviceToDevice);

    void* pa;
    #define SYM(var, sym) cudaGetSymbolAddress(&pa, sym); auto var = (decltype(&sym[0]))pa;
    SYM(Qb, g_Q) SYM(Kb, g_Kb) SYM(Vb, g_Vb) SYM(Gg, g_Gb)
    SYM(lnh, g_lnh) SYM(lnl, g_lnl)
    SYM(cth, g_cth) SYM(ctl, g_ctl)
    SYM(hidh, g_hidh) SYM(hidl, g_hidl)
    SYM(b56, g_b56)
    SYM(wqh, g_WqTh) SYM(wql, g_WqTl) SYM(wkh, g_WkTh) SYM(wkl, g_WkTl)
    SYM(wvh, g_WvTh) SYM(wvl, g_WvTl) SYM(gwh, g_GwTh) SYM(gwl, g_GwTl)
    SYM(owh, g_OwTh) SYM(owl, g_OwTl)
    SYM(w1h, g_w1Th) SYM(w1l, g_w1Tl) SYM(w2h, g_w2Th) SYM(w2l, g_w2Tl)
    SYM(w56h, g_W56h) SYM(w56l, g_W56l)
    #undef SYM

    cudaFuncSetAttribute(gemm_batched, cudaFuncAttributeMaxDynamicSharedMemorySize, GSMEM);

    // ---- weight prep ----
    {
        dim3 gA(DD/32, DD/32, 7);
        wsplit_kernel<<<gA, 256>>>(aWq, wqh, wql, DD, DD, DD, 0, DD*DD, DD*DD);
        wsplit_kernel<<<gA, 256>>>(aWk, wkh, wkl, DD, DD, DD, 0, DD*DD, DD*DD);
        wsplit_kernel<<<gA, 256>>>(aWv, wvh, wvl, DD, DD, DD, 0, DD*DD, DD*DD);
        wsplit_kernel<<<gA, 256>>>(aGw, gwh, gwl, DD, DD, DD, 0, DD*DD, DD*DD);
        wsplit_kernel<<<gA, 256>>>(aOw, owh, owl, DD, DD, DD, 0, DD*DD, DD*DD);
        dim3 g1(HID/32, DD/32, 6);
        wsplit_kernel<<<g1, 256>>>(ff_w1, w1h, w1l, DD, HID, DD, 0, (long long)DD*HID, (long long)DD*HID);
        dim3 g2(DD/32, HID/32, 6);
        wsplit_kernel<<<g2, 256>>>(ff_w2, w2h, w2l, HID, DD, HID, 0, (long long)HID*DD, (long long)HID*DD);
        dim3 g56(DD/32, DD/32, 1);
        wsplit_kernel<<<g56, 256>>>(aOw + (size_t)5*DD*DD, w56h, w56l, DD, DD, 512, 0, 0, 0);
        wsplit_kernel<<<g56, 256>>>(aOw + (size_t)6*DD*DD, w56h, w56l, DD, DD, 512, 256, 0, 0);
        b56_kernel<<<1, DD>>>(aOb);
    }

    float* QKVG[4] = { Qb, Kb, Vb, Gg };

    auto run_ln = [&](int nz, const float* xs[], const float* gbase, const float* bbase,
                      const int* ks, const int* slots) {
        LnBatch lb;
        for (int j = 0; j < nz; j++)
            lb.s[j] = { xs[j], gbase + (size_t)ks[j]*DD, bbase + (size_t)ks[j]*DD,
                        lnh + (size_t)slots[j]*BSD, lnl + (size_t)slots[j]*BSD };
        ln_kernel<<<dim3(MM, nz), 256>>>(lb);
    };

    auto run_qkvg = [&](int nz, const int* mods, const int* qslot, const int* kvslot) {
        Batch bt = {};
        for (int j = 0; j < nz; j++) {
            int k = mods[j];
            for (int c = 0; c < 4; c++) {
                Slice& s = bt.s[j*4 + c];
                int slot = (c == 0) ? qslot[j] : kvslot[j];
                s.Ah = lnh + (size_t)slot*BSD;
                s.Al = lnl + (size_t)slot*BSD;
                const bf16* bh[4] = { wqh, wkh, wvh, gwh };
                const bf16* bl[4] = { wql, wkl, wvl, gwl };
                s.Bh = bh[c] + (size_t)k*DD*DD;
                s.Bl = bl[c] + (size_t)k*DD*DD;
                s.bias = (c == 3) ? (aGb + (size_t)k*DD) : nullptr;
                s.C = QKVG[c] + (size_t)j*BSD;
                s.mode = (c == 3) ? 2 : 0;
            }
        }
        gemm_batched<<<dim3(DD/128, MM/128, nz*4), 256, GSMEM>>>(bt, MM, DD, DD);
    };

    auto run_attn = [&](int nz) {
        AtBatch ab = {};
        for (int j = 0; j < nz; j++)
            ab.s[j] = { Qb + (size_t)j*BSD, Kb + (size_t)j*BSD, Vb + (size_t)j*BSD,
                        Gg + (size_t)j*BSD, cth + (size_t)j*BSD, ctl + (size_t)j*BSD };
        attn_core_kernel<<<dim3((BB*HH*SS*32)/256, nz), 256>>>(ab, mask);
    };

    auto run_proj = [&](int nz, const int* mods, float* const* dst) {
        Batch bt = {};
        for (int j = 0; j < nz; j++) {
            int k = mods[j];
            Slice& s = bt.s[j];
            s.Ah = cth + (size_t)j*BSD;
            s.Al = ctl + (size_t)j*BSD;
            s.Bh = owh + (size_t)k*DD*DD;
            s.Bl = owl + (size_t)k*DD*DD;
            s.bias = aOb + (size_t)k*DD;
            s.res = dst[j]; s.C = dst[j];
        }
        gemm_batched<<<dim3(DD/128, MM/128, nz), 256, GSMEM>>>(bt, MM, DD, DD);
    };

    auto run_ff = [&](int nz, const int* mods, float* const* dst) {
        LnBatch lb;
        for (int j = 0; j < nz; j++)
            lb.s[j] = { dst[j], ff_g + (size_t)mods[j]*DD, ff_b + (size_t)mods[j]*DD,
                        lnh + (size_t)j*BSD, lnl + (size_t)j*BSD };
        ln_kernel<<<dim3(MM, nz), 256>>>(lb);
        Batch b1 = {};
        for (int j = 0; j < nz; j++) {
            Slice& s = b1.s[j];
            s.Ah = lnh + (size_t)j*BSD; s.Al = lnl + (size_t)j*BSD;
            s.Bh = w1h + (size_t)mods[j]*DD*HID; s.Bl = w1l + (size_t)mods[j]*DD*HID;
            s.bias = ff_b1 + (size_t)mods[j]*HID;
            s.Ch = hidh + (size_t)j*MH; s.Cl = hidl + (size_t)j*MH;
            s.mode = 1;
        }
        gemm_batched<<<dim3(HID/128, MM/128, nz), 256, GSMEM>>>(b1, MM, HID, DD);
        Batch b2 = {};
        for (int j = 0; j < nz; j++) {
            Slice& s = b2.s[j];
            s.Ah = hidh + (size_t)j*MH; s.Al = hidl + (size_t)j*MH;
            s.Bh = w2h + (size_t)mods[j]*HID*DD; s.Bl = w2l + (size_t)mods[j]*HID*DD;
            s.bias = ff_b2 + (size_t)mods[j]*DD;
            s.res = dst[j]; s.C = dst[j];
        }
        gemm_batched<<<dim3(DD/128, MM/128, nz), 256, GSMEM>>>(b2, MM, DD, HID);
    };

    for (int it = 0; it < NITER; it++) {
        {
            const float* xs[3] = { L, Nb, O };
            const int lnk[3] = { 0, 1, 2 };
            const int slots[3] = { 0, 1, 2 };
            run_ln(3, xs, ln_g, ln_b, lnk, slots);
            const int mods[3] = { 0, 1, 2 };
            run_qkvg(3, mods, slots, slots);
            run_attn(3);
            run_proj(3, mods, X);
            run_ff(3, mods, X);
        }
        {
            const float* xs[3] = { O, L, Nb };
            const int lnk[3] = { 3, 4, 5 };
            const int slots[3] = { 3, 0, 1 };
            run_ln(3, xs, ln_g, ln_b, lnk, slots);
            const int mods[2] = { 3, 4 };
            const int qslot[2] = { 0, 1 };
            const int kvslot[2] = { 3, 3 };
            run_qkvg(2, mods, qslot, kvslot);
            run_attn(2);
            float* dst[2] = { L, Nb };
            run_proj(2, mods, dst);
            run_ff(2, mods, dst);
        }
        {
            const float* xs[3] = { L, Nb, O };
            const int lnk[3] = { 6, 7, 8 };
            const int slots[3] = { 0, 1, 2 };
            run_ln(3, xs, ln_g, ln_b, lnk, slots);
            const int mods[2] = { 5, 6 };
            const int qslot[2] = { 2, 2 };
            const int kvslot[2] = { 1, 0 };
            run_qkvg(2, mods, qslot, kvslot);
            run_attn(2);
            Batch bp = {};
            bp.s[0].Ah = cth; bp.s[0].Al = ctl;
            bp.s[0].A2h = cth + BSD; bp.s[0].A2l = ctl + BSD;
            bp.s[0].Bh = w56h; bp.s[0].Bl = w56l;
            bp.s[0].bias = b56; bp.s[0].res = O; bp.s[0].C = O;
            gemm_batched<<<dim3(DD/128, MM/128, 1), 256, GSMEM>>>(bp, MM, DD, 512);
            const int ffm[1] = { 5 };
            float* dst[1] = { O };
            run_ff(1, ffm, dst);
        }
    }
}

// round 10
// speedup vs baseline: 3.7307x; 1.2611x over previous
#include <cuda_runtime.h>
#include <cuda_bf16.h>
#include <stdint.h>
#include <math.h>

#define BB 2
#define SS 1024
#define DD 256
#define HH 4
#define CC 64
#define WINSZ 10
#define NITER 2
#define MM 2048
#define HID 2048
#define BSD (BB*SS*DD)
#define MH ((size_t)MM*HID)
#define MD ((size_t)MM*DD)

typedef __nv_bfloat16 bf16;

// ---------------- scratch (device globals; no allocation) -------------------
__device__ float g_Q[3*BSD], g_Kb[3*BSD], g_Vb[3*BSD], g_Gb[3*BSD];
__device__ float g_b56[DD];
__device__ float g_part[12*MD];                       // split-K partials
__device__ bf16 g_lnh[4*BSD], g_lnl[4*BSD];
__device__ bf16 g_cth[3*BSD], g_ctl[3*BSD];
__device__ bf16 g_hidh[3*MH], g_hidl[3*MH];

__device__ bf16 g_WqTh[7*DD*DD], g_WqTl[7*DD*DD];
__device__ bf16 g_WkTh[7*DD*DD], g_WkTl[7*DD*DD];
__device__ bf16 g_WvTh[7*DD*DD], g_WvTl[7*DD*DD];
__device__ bf16 g_GwTh[7*DD*DD], g_GwTl[7*DD*DD];
__device__ bf16 g_OwTh[7*DD*DD], g_OwTl[7*DD*DD];
__device__ bf16 g_w1Th[(size_t)6*DD*HID], g_w1Tl[(size_t)6*DD*HID];
__device__ bf16 g_w2Th[(size_t)6*HID*DD], g_w2Tl[(size_t)6*HID*DD];

__device__ __forceinline__ void split2(float v, bf16& h, bf16& l){
    h = __float2bfloat16(v);
    l = __float2bfloat16(v - __bfloat162float(h));
}
__device__ __forceinline__ uint32_t smem_u32(const void* p){
    uint32_t a;
    asm("{ .reg .u64 t; cvta.to.shared.u64 t, %1; cvt.u32.u64 %0, t; }" : "=r"(a) : "l"(p));
    return a;
}
__device__ __forceinline__ void cp16(uint32_t saddr, const void* g){
    asm volatile("cp.async.cg.shared.global [%0], [%1], 16;" :: "r"(saddr), "l"(g));
}
__device__ __forceinline__ void ldsm_x4(uint32_t* r, uint32_t addr){
    asm volatile("ldmatrix.sync.aligned.m8n8.x4.shared.b16 {%0,%1,%2,%3}, [%4];"
        : "=r"(r[0]), "=r"(r[1]), "=r"(r[2]), "=r"(r[3]) : "r"(addr));
}

// ---------------- weight transpose + split ----------------------------------
// generic body: W[K,N] fp32 -> Th/Tl [N][ldt] at ooff
__device__ __forceinline__ void wsplit_body(
    const float* w, bf16* th, bf16* tl, int N, int ldt, int ooff)
{
    __shared__ float sm[32][33];
    int n0 = blockIdx.x * 32, k0 = blockIdx.y * 32;
    int tx = threadIdx.x & 31, ty = threadIdx.x >> 5;
    #pragma unroll
    for (int i = 0; i < 4; i++)
        sm[ty + i*8][tx] = w[(size_t)(k0 + ty + i*8) * N + n0 + tx];
    __syncthreads();
    #pragma unroll
    for (int i = 0; i < 4; i++) {
        int n = n0 + ty + i*8;
        bf16 h, l; split2(sm[tx][ty + i*8], h, l);
        th[(size_t)n * ldt + ooff + k0 + tx] = h;
        tl[(size_t)n * ldt + ooff + k0 + tx] = l;
    }
}

struct WsAll { const float* src[5]; bf16* th[5]; bf16* tl[5]; };
// z = fam*7 + module, 35 slices of DDxDD
__global__ void __launch_bounds__(256) wsplit_all(WsAll wa)
{
    int fam = blockIdx.z / 7, mod = blockIdx.z % 7;
    wsplit_body(wa.src[fam] + (size_t)mod*DD*DD,
                wa.th[fam] + (size_t)mod*DD*DD, wa.tl[fam] + (size_t)mod*DD*DD,
                DD, DD, 0);
}
__global__ void __launch_bounds__(256) wsplit_big(
    const float* __restrict__ W, bf16* __restrict__ Th, bf16* __restrict__ Tl,
    int K, int N, long long wstride, long long tstride)
{
    wsplit_body(W + (size_t)blockIdx.z * wstride,
                Th + (size_t)blockIdx.z * tstride, Tl + (size_t)blockIdx.z * tstride,
                N, K, 0);
}
__global__ void b56_kernel(const float* __restrict__ aOb){
    int t = threadIdx.x;
    g_b56[t] = aOb[5*DD + t] + aOb[6*DD + t];
}

// ---------------- LayerNorm (batched over z), split bf16 output -------------
struct LnS { const float* x; const float* g; const float* b; bf16* oh; bf16* ol; };
struct LnBatch { LnS s[3]; };

__global__ void __launch_bounds__(256) ln_kernel(LnBatch lb)
{
    LnS sl = lb.s[blockIdx.y];
    int row = blockIdx.x;
    int t   = threadIdx.x;
    float v = sl.x[(size_t)row * DD + t];
    __shared__ float red[8];
    __shared__ float mean_s, rstd_s;
    float s = v;
    #pragma unroll
    for (int o = 16; o > 0; o >>= 1) s += __shfl_xor_sync(0xffffffffu, s, o);
    if ((t & 31) == 0) red[t >> 5] = s;
    __syncthreads();
    if (t == 0) { float tot=0.f; for (int i=0;i<8;i++) tot+=red[i]; mean_s = tot*(1.0f/DD); }
    __syncthreads();
    float d = v - mean_s;
    s = d * d;
    #pragma unroll
    for (int o = 16; o > 0; o >>= 1) s += __shfl_xor_sync(0xffffffffu, s, o);
    if ((t & 31) == 0) red[t >> 5] = s;
    __syncthreads();
    if (t == 0) { float tot=0.f; for (int i=0;i<8;i++) tot+=red[i]; rstd_s = rsqrtf(tot*(1.0f/DD)+1e-5f); }
    __syncthreads();
    float out = d * rstd_s * sl.g[t] + sl.b[t];
    bf16 h, l; split2(out, h, l);
    sl.oh[(size_t)row * DD + t] = h;
    sl.ol[(size_t)row * DD + t] = l;
}

// ---------------- split-K reduce: dst = sum(partials) + bias + res ----------
struct RdS { const float* p; const float* bias; const float* res; float* dst; int nsplit; };
struct RdBatch { RdS s[3]; };

__global__ void __launch_bounds__(256) reduce_kernel(RdBatch rb)
{
    RdS sl = rb.s[blockIdx.y];
    size_t idx = ((size_t)blockIdx.x * 256 + threadIdx.x) * 4;
    float4 a = *(const float4*)&sl.p[idx];
    for (int s = 1; s < sl.nsplit; s++) {
        float4 b = *(const float4*)&sl.p[(size_t)s * MD + idx];
        a.x += b.x; a.y += b.y; a.z += b.z; a.w += b.w;
    }
    int col = (int)(idx & (DD - 1));
    float4 bi = *(const float4*)&sl.bias[col];
    a.x += bi.x; a.y += bi.y; a.z += bi.z; a.w += bi.w;
    float4 r4 = *(const float4*)&sl.res[idx];
    a.x += r4.x; a.y += r4.y; a.z += r4.z; a.w += r4.w;
    *(float4*)&sl.dst[idx] = a;
}

// ---------------- batched split-compensated MMA GEMM ------------------------
struct Slice {
    const bf16 *Ah, *Al, *Bh, *Bl;
    const float *bias, *res;
    float* C; bf16 *Ch, *Cl;
    int mode, lda, ldb, Ksub;
};
struct Batch { Slice s[12]; };

#define BKC 32
#define LDSB 40
#define ARRE (128*LDSB)
#define STGE (4*ARRE)
#define GSMEM (2*STGE*2)

__device__ __forceinline__ void mma16816(float* c, const uint32_t* a, const uint32_t* b){
    asm volatile("mma.sync.aligned.m16n8k16.row.col.f32.bf16.bf16.f32 "
        "{%0,%1,%2,%3}, {%4,%5,%6,%7}, {%8,%9}, {%0,%1,%2,%3};"
        : "+f"(c[0]), "+f"(c[1]), "+f"(c[2]), "+f"(c[3])
        : "r"(a[0]), "r"(a[1]), "r"(a[2]), "r"(a[3]), "r"(b[0]), "r"(b[1]));
}

__global__ void __launch_bounds__(256,2)
gemm_batched(Batch bt, int M, int N)
{
    extern __shared__ __align__(16) bf16 smem[];
    const Slice sl = bt.s[blockIdx.z];
    const int tid  = threadIdx.x;
    const int warp = tid >> 5, lane = tid & 31;
    const int wm = warp >> 2, wn = warp & 3;
    const int row0 = blockIdx.y * 128, col0 = blockIdx.x * 128;
    const int g8 = lane >> 2, tig = lane & 3;
    const uint32_t sb = smem_u32(smem);
    const int NC = sl.Ksub / BKC;
    const int lda = sl.lda, ldb = sl.ldb;

    float acc[4][4][4];
    #pragma unroll
    for (int i=0;i<4;i++) for (int j=0;j<4;j++) for (int q=0;q<4;q++) acc[i][j][q]=0.f;

    const int ck0 = tid, ck1 = tid + 256;
    const int r0c = ck0 >> 2, c0c = (ck0 & 3) * 8;
    const int r1c = ck1 >> 2, c1c = (ck1 & 3) * 8;

    const int lmat = lane >> 3, lrow = lane & 7;
    const uint32_t a_lane_off = (uint32_t)(((lmat & 1) * 8 + lrow) * LDSB + (lmat >> 1) * 8) * 2;
    const uint32_t b_lane_off = (uint32_t)(((lmat >> 1) * 8 + lrow) * LDSB + (lmat & 1) * 8) * 2;

    auto cpStage = [&](int c, int st){
        int kc = c * BKC;
        uint32_t base = sb + (uint32_t)(st * STGE) * 2;
        uint32_t so0 = (uint32_t)(r0c * LDSB + c0c) * 2;
        uint32_t so1 = (uint32_t)(r1c * LDSB + c1c) * 2;
        cp16(base + so0,            sl.Ah + (size_t)(row0 + r0c) * lda + kc + c0c);
        cp16(base + so1,            sl.Ah + (size_t)(row0 + r1c) * lda + kc + c1c);
        cp16(base + ARRE*2 + so0,   sl.Al + (size_t)(row0 + r0c) * lda + kc + c0c);
        cp16(base + ARRE*2 + so1,   sl.Al + (size_t)(row0 + r1c) * lda + kc + c1c);
        cp16(base + ARRE*4 + so0,   sl.Bh + (size_t)(col0 + r0c) * ldb + kc + c0c);
        cp16(base + ARRE*4 + so1,   sl.Bh + (size_t)(col0 + r1c) * ldb + kc + c1c);
        cp16(base + ARRE*6 + so0,   sl.Bl + (size_t)(col0 + r0c) * ldb + kc + c0c);
        cp16(base + ARRE*6 + so1,   sl.Bl + (size_t)(col0 + r1c) * ldb + kc + c1c);
        asm volatile("cp.async.commit_group;" ::: "memory");
    };

    cpStage(0, 0);
    if (NC > 1) cpStage(1, 1);
    else asm volatile("cp.async.commit_group;" ::: "memory");

    for (int c = 0; c < NC; c++) {
        const int st = c & 1;
        if (c + 2 < NC) asm volatile("cp.async.wait_group 1;" ::: "memory");
        else            asm volatile("cp.async.wait_group 0;" ::: "memory");
        __syncthreads();

        const uint32_t sA_h = sb + (uint32_t)(st*STGE) * 2;
        const uint32_t sA_l = sA_h + ARRE*2;
        const uint32_t sB_h = sA_h + ARRE*4;
        const uint32_t sB_l = sA_h + ARRE*6;

        #pragma unroll
        for (int kk = 0; kk < 2; kk++) {
            const uint32_t kbo = (uint32_t)(kk * 16) * 2;
            uint32_t bh[4][2], bl[4][2];
            #pragma unroll
            for (int pr = 0; pr < 2; pr++) {
                uint32_t nbase = (uint32_t)((wn*32 + pr*16) * LDSB) * 2;
                uint32_t r4[4];
                ldsm_x4(r4, sB_h + nbase + kbo + b_lane_off);
                bh[pr*2][0] = r4[0]; bh[pr*2][1] = r4[1];
                bh[pr*2+1][0] = r4[2]; bh[pr*2+1][1] = r4[3];
                ldsm_x4(r4, sB_l + nbase + kbo + b_lane_off);
                bl[pr*2][0] = r4[0]; bl[pr*2][1] = r4[1];
                bl[pr*2+1][0] = r4[2]; bl[pr*2+1][1] = r4[3];
            }
            #pragma unroll
            for (int mi = 0; mi < 4; mi++) {
                uint32_t rbase = (uint32_t)((wm*64 + mi*16) * LDSB) * 2;
                uint32_t ah[4], al[4];
                ldsm_x4(ah, sA_h + rbase + kbo + a_lane_off);
                ldsm_x4(al, sA_l + rbase + kbo + a_lane_off);
                #pragma unroll
                for (int ni = 0; ni < 4; ni++) {
                    mma16816(acc[mi][ni], ah, bh[ni]);
                    mma16816(acc[mi][ni], ah, bl[ni]);
                    mma16816(acc[mi][ni], al, bh[ni]);
                }
            }
        }
        __syncthreads();
        if (c + 2 < NC) cpStage(c + 2, st);
    }

    #pragma unroll
    for (int mi = 0; mi < 4; mi++) {
        #pragma unroll
        for (int ni = 0; ni < 4; ni++) {
            int r1 = row0 + wm*64 + mi*16 + g8;
            int c1 = col0 + wn*32 + ni*8 + tig*2;
            #pragma unroll
            for (int q = 0; q < 4; q++) {
                int r = (q < 2) ? r1 : r1 + 8;
                int cc = c1 + (q & 1);
                float v = acc[mi][ni][q];
                if (sl.bias) v += sl.bias[cc];
                if (sl.mode == 1)      v = fmaxf(v, 0.f);
                else if (sl.mode == 2) v = 1.f / (1.f + __expf(-v));
                if (sl.Ch) {
                    bf16 h, l; split2(v, h, l);
                    sl.Ch[(size_t)r * N + cc] = h;
                    sl.Cl[(size_t)r * N + cc] = l;
                } else {
                    if (sl.res) v += sl.res[(size_t)r * N + cc];
                    sl.C[(size_t)r * N + cc] = v;
                }
            }
        }
    }
}

// ---------------- windowed attention core (batched over z) ------------------
struct AtS { const float* Q; const float* K; const float* V; const float* G;
             bf16* cth; bf16* ctl; };
struct AtBatch { AtS s[3]; };

__global__ void __launch_bounds__(256)
attn_core_kernel(AtBatch ab, const unsigned char* __restrict__ mask)
{
    AtS sl = ab.s[blockIdx.y];
    int idx  = blockIdx.x * blockDim.x + threadIdx.x;
    int gw   = idx >> 5;
    int lane = idx & 31;
    int s = gw & (SS - 1);
    int h = (gw >> 10) & (HH - 1);
    int n = gw >> 12;

    int base_q = (n * SS + s) * DD + h * CC;
    float q0 = sl.Q[base_q + lane];
    float q1 = sl.Q[base_q + 32 + lane];

    int t0 = s - WINSZ; if (t0 < 0) t0 = 0;
    int t1 = s + WINSZ; if (t1 > SS - 1) t1 = SS - 1;
    int cnt = t1 - t0 + 1;

    float sc[2 * WINSZ + 1];
    float mx = -1e30f;
    for (int i = 0; i < cnt; i++) {
        int t = t0 + i;
        float v;
        if (mask[n * SS + t]) v = -1e30f;
        else {
            int bk = (n * SS + t) * DD + h * CC;
            float p = q0 * sl.K[bk + lane] + q1 * sl.K[bk + 32 + lane];
            #pragma unroll
            for (int o = 16; o > 0; o >>= 1) p += __shfl_xor_sync(0xffffffffu, p, o);
            v = p * 0.125f;
        }
        sc[i] = v;
        mx = fmaxf(mx, v);
    }
    float denom = 0.f;
    for (int i = 0; i < cnt; i++) {
        float e = (sc[i] <= -1e29f) ? 0.f : __expf(sc[i] - mx);
        sc[i] = e; denom += e;
    }
    float inv = (denom > 0.f) ? (1.f / denom) : 0.f;
    float o0 = 0.f, o1 = 0.f;
    for (int i = 0; i < cnt; i++) {
        int bv = (n * SS + (t0 + i)) * DD + h * CC;
        float a = sc[i] * inv;
        o0 = fmaf(a, sl.V[bv + lane], o0);
        o1 = fmaf(a, sl.V[bv + 32 + lane], o1);
    }
    float v0 = o0 * sl.G[base_q + lane];
    float v1 = o1 * sl.G[base_q + 32 + lane];
    bf16 h0, l0, h1, l1;
    split2(v0, h0, l0); split2(v1, h1, l1);
    sl.cth[base_q + lane]      = h0;  sl.ctl[base_q + lane]      = l0;
    sl.cth[base_q + 32 + lane] = h1;  sl.ctl[base_q + 32 + lane] = l1;
}

// ---------------- host orchestration ----------------------------------------
extern "C" void kernel_launch(void* const* d_in, const int* in_sizes, int n_in,
                              void* d_out, int out_size)
{
    (void)in_sizes; (void)n_in; (void)out_size;
    const float* inL = (const float*)d_in[0];
    const float* inN = (const float*)d_in[1];
    const float* inO = (const float*)d_in[2];
    const unsigned char* mask = (const unsigned char*)d_in[3];
    const float* aWq = (const float*)d_in[4];
    const float* aWk = (const float*)d_in[5];
    const float* aWv = (const float*)d_in[6];
    const float* aGw = (const float*)d_in[7];
    const float* aGb = (const float*)d_in[8];
    const float* aOw = (const float*)d_in[9];
    const float* aOb = (const float*)d_in[10];
    const float* ln_g = (const float*)d_in[11];
    const float* ln_b = (const float*)d_in[12];
    const float* ff_g = (const float*)d_in[13];
    const float* ff_b = (const float*)d_in[14];
    const float* ff_w1 = (const float*)d_in[15];
    const float* ff_b1 = (const float*)d_in[16];
    const float* ff_w2 = (const float*)d_in[17];
    const float* ff_b2 = (const float*)d_in[18];

    float* L  = (float*)d_out;
    float* Nb = L + BSD;
    float* O  = Nb + BSD;
    float* X[3] = { L, Nb, O };

    cudaMemcpyAsync(L,  inL, (size_t)BSD * sizeof(float), cudaMemcpyDeviceToDevice);
    cudaMemcpyAsync(Nb, inN, (size_t)BSD * sizeof(float), cudaMemcpyDeviceToDevice);
    cudaMemcpyAsync(O,  inO, (size_t)BSD * sizeof(float), cudaMemcpyDeviceToDevice);

    void* pa;
    #define SYM(var, sym) cudaGetSymbolAddress(&pa, sym); auto var = (decltype(&sym[0]))pa;
    SYM(Qb, g_Q) SYM(Kb, g_Kb) SYM(Vb, g_Vb) SYM(Gg, g_Gb)
    SYM(lnh, g_lnh) SYM(lnl, g_lnl)
    SYM(cth, g_cth) SYM(ctl, g_ctl)
    SYM(hidh, g_hidh) SYM(hidl, g_hidl)
    SYM(b56, g_b56) SYM(part, g_part)
    SYM(wqh, g_WqTh) SYM(wql, g_WqTl) SYM(wkh, g_WkTh) SYM(wkl, g_WkTl)
    SYM(wvh, g_WvTh) SYM(wvl, g_WvTl) SYM(gwh, g_GwTh) SYM(gwl, g_GwTl)
    SYM(owh, g_OwTh) SYM(owl, g_OwTl)
    SYM(w1h, g_w1Th) SYM(w1l, g_w1Tl) SYM(w2h, g_w2Th) SYM(w2l, g_w2Tl)
    #undef SYM

    cudaFuncSetAttribute(gemm_batched, cudaFuncAttributeMaxDynamicSharedMemorySize, GSMEM);

    // ---- weight prep: 4 launches ----
    {
        WsAll wa;
        wa.src[0]=aWq; wa.src[1]=aWk; wa.src[2]=aWv; wa.src[3]=aGw; wa.src[4]=aOw;
        wa.th[0]=wqh; wa.th[1]=wkh; wa.th[2]=wvh; wa.th[3]=gwh; wa.th[4]=owh;
        wa.tl[0]=wql; wa.tl[1]=wkl; wa.tl[2]=wvl; wa.tl[3]=gwl; wa.tl[4]=owl;
        wsplit_all<<<dim3(8, 8, 35), 256>>>(wa);
        wsplit_big<<<dim3(HID/32, DD/32, 6), 256>>>(ff_w1, w1h, w1l, DD, HID,
                                                    (long long)DD*HID, (long long)DD*HID);
        wsplit_big<<<dim3(DD/32, HID/32, 6), 256>>>(ff_w2, w2h, w2l, HID, DD,
                                                    (long long)HID*DD, (long long)HID*DD);
        b56_kernel<<<1, DD>>>(aOb);
    }

    float* QKVG[4] = { Qb, Kb, Vb, Gg };

    auto run_ln = [&](int nz, const float* xs[], const float* gbase, const float* bbase,
                      const int* ks, const int* slots) {
        LnBatch lb;
        for (int j = 0; j < nz; j++)
            lb.s[j] = { xs[j], gbase + (size_t)ks[j]*DD, bbase + (size_t)ks[j]*DD,
                        lnh + (size_t)slots[j]*BSD, lnl + (size_t)slots[j]*BSD };
        ln_kernel<<<dim3(MM, nz), 256>>>(lb);
    };

    auto run_qkvg = [&](int nz, const int* mods, const int* qslot, const int* kvslot) {
        Batch bt = {};
        for (int j = 0; j < nz; j++) {
            int k = mods[j];
            for (int c = 0; c < 4; c++) {
                Slice& s = bt.s[j*4 + c];
                int slot = (c == 0) ? qslot[j] : kvslot[j];
                s.Ah = lnh + (size_t)slot*BSD;
                s.Al = lnl + (size_t)slot*BSD;
                const bf16* bh[4] = { wqh, wkh, wvh, gwh };
                const bf16* bl[4] = { wql, wkl, wvl, gwl };
                s.Bh = bh[c] + (size_t)k*DD*DD;
                s.Bl = bl[c] + (size_t)k*DD*DD;
                s.bias = (c == 3) ? (aGb + (size_t)k*DD) : nullptr;
                s.C = QKVG[c] + (size_t)j*BSD;
                s.mode = (c == 3) ? 2 : 0;
                s.lda = DD; s.ldb = DD; s.Ksub = DD;
            }
        }
        gemm_batched<<<dim3(DD/128, MM/128, nz*4), 256, GSMEM>>>(bt, MM, DD);
    };

    auto run_attn = [&](int nz) {
        AtBatch ab = {};
        for (int j = 0; j < nz; j++)
            ab.s[j] = { Qb + (size_t)j*BSD, Kb + (size_t)j*BSD, Vb + (size_t)j*BSD,
                        Gg + (size_t)j*BSD, cth + (size_t)j*BSD, ctl + (size_t)j*BSD };
        attn_core_kernel<<<dim3((BB*HH*SS*32)/256, nz), 256>>>(ab, mask);
    };

    auto run_proj = [&](int nz, const int* mods, float* const* dst) {
        Batch bt = {};
        for (int j = 0; j < nz; j++) {
            int k = mods[j];
            Slice& s = bt.s[j];
            s.Ah = cth + (size_t)j*BSD;
            s.Al = ctl + (size_t)j*BSD;
            s.Bh = owh + (size_t)k*DD*DD;
            s.Bl = owl + (size_t)k*DD*DD;
            s.bias = aOb + (size_t)k*DD;
            s.res = dst[j]; s.C = dst[j];
            s.lda = DD; s.ldb = DD; s.Ksub = DD;
        }
        gemm_batched<<<dim3(DD/128, MM/128, nz), 256, GSMEM>>>(bt, MM, DD);
    };

    auto run_ff = [&](int nz, const int* mods, float* const* dst) {
        LnBatch lb;
        for (int j = 0; j < nz; j++)
            lb.s[j] = { dst[j], ff_g + (size_t)mods[j]*DD, ff_b + (size_t)mods[j]*DD,
                        lnh + (size_t)j*BSD, lnl + (size_t)j*BSD };
        ln_kernel<<<dim3(MM, nz), 256>>>(lb);
        // FF1 (relu, split output)
        Batch b1 = {};
        for (int j = 0; j < nz; j++) {
            Slice& s = b1.s[j];
            s.Ah = lnh + (size_t)j*BSD; s.Al = lnl + (size_t)j*BSD;
            s.Bh = w1h + (size_t)mods[j]*DD*HID; s.Bl = w1l + (size_t)mods[j]*DD*HID;
            s.bias = ff_b1 + (size_t)mods[j]*HID;
            s.Ch = hidh + (size_t)j*MH; s.Cl = hidl + (size_t)j*MH;
            s.mode = 1; s.lda = DD; s.ldb = DD; s.Ksub = DD;
        }
        gemm_batched<<<dim3(HID/128, MM/128, nz), 256, GSMEM>>>(b1, MM, HID);
        // FF2 split-K into 4 partials
        Batch b2 = {};
        for (int j = 0; j < nz; j++)
            for (int sp = 0; sp < 4; sp++) {
                Slice& s = b2.s[j*4 + sp];
                s.Ah = hidh + (size_t)j*MH + sp*512;
                s.Al = hidl + (size_t)j*MH + sp*512;
                s.Bh = w2h + (size_t)mods[j]*HID*DD + sp*512;
                s.Bl = w2l + (size_t)mods[j]*HID*DD + sp*512;
                s.C = part + (size_t)(j*4 + sp)*MD;
                s.lda = HID; s.ldb = HID; s.Ksub = 512;
            }
        gemm_batched<<<dim3(DD/128, MM/128, nz*4), 256, GSMEM>>>(b2, MM, DD);
        // reduce: dst = sum(partials) + bias + res(dst)
        RdBatch rb = {};
        for (int j = 0; j < nz; j++)
            rb.s[j] = { part + (size_t)j*4*MD, ff_b2 + (size_t)mods[j]*DD,
                        dst[j], dst[j], 4 };
        reduce_kernel<<<dim3((int)(MD/1024), nz), 256>>>(rb);
    };

    for (int it = 0; it < NITER; it++) {
        // -------- Phase 1: self blocks --------
        {
            const float* xs[3] = { L, Nb, O };
            const int lnk[3] = { 0, 1, 2 };
            const int slots[3] = { 0, 1, 2 };
            run_ln(3, xs, ln_g, ln_b, lnk, slots);
            const int mods[3] = { 0, 1, 2 };
            run_qkvg(3, mods, slots, slots);
            run_attn(3);
            run_proj(3, mods, X);
            run_ff(3, mods, X);
        }
        // -------- Phase 2: cross blocks --------
        {
            const float* xs[3] = { O, L, Nb };
            const int lnk[3] = { 3, 4, 5 };
            const int slots[3] = { 3, 0, 1 };
            run_ln(3, xs, ln_g, ln_b, lnk, slots);
            const int mods[2] = { 3, 4 };
            const int qslot[2] = { 0, 1 };
            const int kvslot[2] = { 3, 3 };
            run_qkvg(2, mods, qslot, kvslot);
            run_attn(2);
            float* dst[2] = { L, Nb };
            run_proj(2, mods, dst);
            run_ff(2, mods, dst);
        }
        // -------- Phase 3: O update --------
        {
            const float* xs[3] = { L, Nb, O };
            const int lnk[3] = { 6, 7, 8 };
            const int slots[3] = { 0, 1, 2 };
            run_ln(3, xs, ln_g, ln_b, lnk, slots);
            const int mods[2] = { 5, 6 };
            const int qslot[2] = { 2, 2 };
            const int kvslot[2] = { 1, 0 };
            run_qkvg(2, mods, qslot, kvslot);
            run_attn(2);
            // proj5 + proj6 as two split slices -> partials -> reduce(b56, res=O)
            Batch bp = {};
            for (int sp = 0; sp < 2; sp++) {
                Slice& s = bp.s[sp];
                s.Ah = cth + (size_t)sp*BSD;
                s.Al = ctl + (size_t)sp*BSD;
                s.Bh = owh + (size_t)(5 + sp)*DD*DD;
                s.Bl = owl + (size_t)(5 + sp)*DD*DD;
                s.C = part + (size_t)sp*MD;
                s.lda = DD; s.ldb = DD; s.Ksub = DD;
            }
            gemm_batched<<<dim3(DD/128, MM/128, 2), 256, GSMEM>>>(bp, MM, DD);
            RdBatch rp = {};
            rp.s[0] = { part, b56, O, O, 2 };
            reduce_kernel<<<dim3((int)(MD/1024), 1), 256>>>(rp);
            const int ffm[1] = { 5 };
            float* dst[1] = { O };
            run_ff(1, ffm, dst);
        }
    }
}